// round 13
// baseline (speedup 1.0000x reference)
#include <cuda_runtime.h>
#include <cuda_fp16.h>
#include <math.h>
#include <stdint.h>

// ---------------------------------------------------------------------------
// Problem constants
// ---------------------------------------------------------------------------
#define BATCH   4
#define SEQ     1024
#define DIM     768
#define HEADS   12
#define HD      64
#define SFULL   2048
#define MTOK    4096
#define QKVN    2304
#define BHSD    ((long)BATCH * HEADS * SFULL * HD)

// ---------------------------------------------------------------------------
// Scratch (__device__ globals; no allocation)
// ---------------------------------------------------------------------------
__device__ __half g_qkv0[(long)MTOK * QKVN];
__device__ __half g_qkv1[(long)MTOK * QKVN];
__device__ __half g_xh[(long)MTOK * DIM];
__device__ __half g_yh[(long)MTOK * DIM];
__device__ __half g_wqx[(long)QKVN * DIM];
__device__ __half g_wqy[(long)QKVN * DIM];
__device__ __half g_wpx[(long)DIM * DIM];
__device__ __half g_wpy[(long)DIM * DIM];
__device__ __half g_Qh[BHSD];
__device__ __half g_Kh[BHSD];
__device__ __half g_Vh[BHSD];
__device__ __half g_Oh[(long)BATCH * SFULL * DIM];

// ---------------------------------------------------------------------------
// mma / ldmatrix / cp.async helpers
// ---------------------------------------------------------------------------
__device__ __forceinline__ void mma_f16(float* d, const uint32_t* a,
                                        uint32_t b0, uint32_t b1) {
    asm volatile(
        "mma.sync.aligned.m16n8k16.row.col.f32.f16.f16.f32 "
        "{%0,%1,%2,%3}, {%4,%5,%6,%7}, {%8,%9}, {%0,%1,%2,%3};\n"
        : "+f"(d[0]), "+f"(d[1]), "+f"(d[2]), "+f"(d[3])
        : "r"(a[0]), "r"(a[1]), "r"(a[2]), "r"(a[3]), "r"(b0), "r"(b1));
}

__device__ __forceinline__ void ldsm4(uint32_t* r, uint32_t addr) {
    asm volatile(
        "ldmatrix.sync.aligned.m8n8.x4.shared.b16 {%0,%1,%2,%3}, [%4];"
        : "=r"(r[0]), "=r"(r[1]), "=r"(r[2]), "=r"(r[3]) : "r"(addr));
}

__device__ __forceinline__ void ldsm4t(uint32_t* r, uint32_t addr) {
    asm volatile(
        "ldmatrix.sync.aligned.m8n8.x4.trans.shared.b16 {%0,%1,%2,%3}, [%4];"
        : "=r"(r[0]), "=r"(r[1]), "=r"(r[2]), "=r"(r[3]) : "r"(addr));
}

__device__ __forceinline__ uint32_t cvta_s(const void* p) {
    return (uint32_t)__cvta_generic_to_shared(p);
}

__device__ __forceinline__ uint32_t packh2(float a, float b) {
    half2 h = __floats2half2_rn(a, b);
    return *(uint32_t*)&h;
}

__device__ __forceinline__ uint32_t h2exp2(uint32_t x) {
    uint32_t r;
    asm("ex2.approx.f16x2 %0, %1;" : "=r"(r) : "r"(x));
    return r;
}

__device__ __forceinline__ void cp16(uint32_t smem, const void* g) {
    asm volatile("cp.async.ca.shared.global [%0], [%1], 16;\n"
                 :: "r"(smem), "l"(g));
}
#define CP_COMMIT() asm volatile("cp.async.commit_group;\n")
#define CP_WAIT(n)  asm volatile("cp.async.wait_group %0;\n" :: "n"(n))

// Typed float2/half2 epilogue store
__device__ __forceinline__ void store2(float* C, long idx, float a, float b) {
    *(float2*)&C[idx] = make_float2(a, b);
}
__device__ __forceinline__ void store2(__half* C, long idx, float a, float b) {
    *(half2*)&C[idx] = __floats2half2_rn(a, b);
}

// ---------------------------------------------------------------------------
// Fused fp32 -> fp16 conversion for all 6 input tensors (one launch)
// ---------------------------------------------------------------------------
#define NXP (MTOK * DIM / 2)
#define NWP (QKVN * DIM / 2)
#define NPP (DIM * DIM / 2)
#define NCVT (2 * NXP + 2 * NWP + 2 * NPP)

__global__ void cvt_all(const float* __restrict__ x, const float* __restrict__ y,
                        const float* __restrict__ wqx, const float* __restrict__ wqy,
                        const float* __restrict__ wpx, const float* __restrict__ wpy,
                        __half* xh, __half* yh, __half* wqxh, __half* wqyh,
                        __half* wpxh, __half* wpyh) {
    int i = blockIdx.x * blockDim.x + threadIdx.x;
    const float* src; __half* dst; int off;
    if (i < NXP)                    { src = x;   dst = xh;   off = i; }
    else if (i < 2 * NXP)           { src = y;   dst = yh;   off = i - NXP; }
    else if (i < 2 * NXP + NWP)     { src = wqx; dst = wqxh; off = i - 2 * NXP; }
    else if (i < 2 * NXP + 2 * NWP) { src = wqy; dst = wqyh; off = i - 2 * NXP - NWP; }
    else if (i < 2 * NXP + 2 * NWP + NPP)
                                    { src = wpx; dst = wpxh; off = i - 2 * NXP - 2 * NWP; }
    else                            { src = wpy; dst = wpyh; off = i - 2 * NXP - 2 * NWP - NPP; }
    float2 v = ((const float2*)src)[off];
    ((half2*)dst)[off] = __floats2half2_rn(v.x, v.y);
}

// ---------------------------------------------------------------------------
// fp16 tensor-core GEMM, cp.async double-buffered, paired x/y via blockIdx.z.
// C[M,N] = A @ B^T + bias (fp32 accum; TO = __half or float output).
// 256 thr = 8 warps (2M x 4N), tile 128x128, BK=32.
// ---------------------------------------------------------------------------
#define GKS 40
#define GST (128 * GKS)

template <typename TO>
__global__ void __launch_bounds__(256) gemm2_h(
        const __half* __restrict__ A0, const __half* __restrict__ A1,
        long a_bstride,
        const __half* __restrict__ B0, const __half* __restrict__ B1,
        const float* __restrict__ bias0, const float* __restrict__ bias1,
        TO* __restrict__ C0, TO* __restrict__ C1, int N, int K) {
    __shared__ __half As[2][GST];
    __shared__ __half Bs[2][GST];

    const int z = blockIdx.z;
    const __half* A  = z ? A1 : A0;
    const __half* Bw = z ? B1 : B0;
    const float* bias = z ? bias1 : bias0;
    TO* C = z ? C1 : C0;

    const int tid = threadIdx.x, lane = tid & 31, w = tid >> 5;
    const int gid = lane >> 2, tig = lane & 3;
    const int bm = blockIdx.y, bn = blockIdx.x;
    const int wm = w & 1, wn = w >> 1;

    const int arow = (lane & 7) + 8 * ((lane >> 3) & 1);
    const int acol = ((lane >> 4) & 1) * 8;
    const int brow = (lane & 7) + 8 * ((lane >> 4) & 1);
    const int bcol = ((lane >> 3) & 1) * 8;

    int row[2], kg[2];
    const __half* ga[2];
    const __half* gb[2];
    uint32_t soff[2];
#pragma unroll
    for (int i = 0; i < 2; i++) {
        int s = i * 256 + tid;
        row[i] = s >> 2;
        kg[i]  = (s & 3) * 8;
        int m = bm * 128 + row[i];
        ga[i] = A + ((long)(m >> 10)) * a_bstride + (long)(m & 1023) * K + kg[i];
        gb[i] = Bw + (long)(bn * 128 + row[i]) * K + kg[i];
        soff[i] = (uint32_t)(row[i] * GKS + kg[i]) * 2;
    }

    const uint32_t as0 = cvta_s(As[0]);
    const uint32_t bs0 = cvta_s(Bs[0]);
    const int nsteps = K / 32;

#pragma unroll
    for (int st = 0; st < 2; st++) {
#pragma unroll
        for (int i = 0; i < 2; i++) {
            cp16(as0 + st * GST * 2 + soff[i], ga[i] + st * 32);
            cp16(bs0 + st * GST * 2 + soff[i], gb[i] + st * 32);
        }
        CP_COMMIT();
    }
    CP_WAIT(1);
    __syncthreads();

    float acc[4][4][4];
#pragma unroll
    for (int mt = 0; mt < 4; mt++)
#pragma unroll
        for (int nt = 0; nt < 4; nt++)
#pragma unroll
            for (int r = 0; r < 4; r++) acc[mt][nt][r] = 0.f;

    for (int kt = 0; kt < nsteps; kt++) {
        const int cur = kt & 1;
        const uint32_t asb = as0 + cur * GST * 2;
        const uint32_t bsb = bs0 + cur * GST * 2;
#pragma unroll
        for (int kc = 0; kc < 2; kc++) {
            uint32_t af[4][4], bf[2][4];
#pragma unroll
            for (int mt = 0; mt < 4; mt++)
                ldsm4(af[mt], asb +
                    ((wm * 64 + mt * 16 + arow) * GKS + kc * 16 + acol) * 2);
#pragma unroll
            for (int p = 0; p < 2; p++)
                ldsm4(bf[p], bsb +
                    ((wn * 32 + p * 16 + brow) * GKS + kc * 16 + bcol) * 2);
#pragma unroll
            for (int mt = 0; mt < 4; mt++)
#pragma unroll
                for (int p = 0; p < 2; p++) {
                    mma_f16(acc[mt][2 * p],     af[mt], bf[p][0], bf[p][1]);
                    mma_f16(acc[mt][2 * p + 1], af[mt], bf[p][2], bf[p][3]);
                }
        }
        __syncthreads();
        if (kt + 2 < nsteps) {
#pragma unroll
            for (int i = 0; i < 2; i++) {
                cp16(as0 + cur * GST * 2 + soff[i], ga[i] + (kt + 2) * 32);
                cp16(bs0 + cur * GST * 2 + soff[i], gb[i] + (kt + 2) * 32);
            }
            CP_COMMIT();
            CP_WAIT(1);
        } else {
            CP_WAIT(0);
        }
        __syncthreads();
    }

#pragma unroll
    for (int mt = 0; mt < 4; mt++) {
        int m0 = bm * 128 + wm * 64 + mt * 16 + gid;
#pragma unroll
        for (int nt = 0; nt < 4; nt++) {
            int n0 = bn * 128 + wn * 32 + nt * 8 + 2 * tig;
            float2 bb = *(const float2*)&bias[n0];
            store2(C, (long)m0 * N + n0,
                   acc[mt][nt][0] + bb.x, acc[mt][nt][1] + bb.y);
            store2(C, (long)(m0 + 8) * N + n0,
                   acc[mt][nt][2] + bb.x, acc[mt][nt][3] + bb.y);
        }
    }
}

// ---------------------------------------------------------------------------
// LayerNorm (q,k) + split into [b, h, 2048, 64] half layout.
// Q output pre-scaled by log2(e)/8 (softmax fold).
// ---------------------------------------------------------------------------
#define SCF 0.180336906f

__device__ __forceinline__ void ln_row_h2(const __half* __restrict__ x,
                                          __half* __restrict__ out,
                                          const float* __restrict__ g,
                                          const float* __restrict__ bb,
                                          int lane, float sc) {
    float2 xv = __half22float2(*(const half2*)(x + 2 * lane));
    float sum = xv.x + xv.y;
#pragma unroll
    for (int o = 16; o; o >>= 1) sum += __shfl_xor_sync(0xffffffffu, sum, o);
    float mu = sum * (1.0f / 64.0f);
    float d0 = xv.x - mu, d1 = xv.y - mu;
    float v = d0 * d0 + d1 * d1;
#pragma unroll
    for (int o = 16; o; o >>= 1) v += __shfl_xor_sync(0xffffffffu, v, o);
    float inv = rsqrtf(v * (1.0f / 64.0f) + 1e-5f);
    float2 gv = *(const float2*)(g + 2 * lane);
    float2 bv = *(const float2*)(bb + 2 * lane);
    float o0 = (d0 * inv * gv.x + bv.x) * sc;
    float o1 = (d1 * inv * gv.y + bv.y) * sc;
    *(half2*)(out + 2 * lane) = __floats2half2_rn(o0, o1);
}

__global__ void ln_split_kernel(const __half* __restrict__ qkv0,
                                const __half* __restrict__ qkv1,
                                __half* __restrict__ Q, __half* __restrict__ Kb,
                                __half* __restrict__ Vb,
                                const float* gqx, const float* bqx,
                                const float* gkx, const float* bkx,
                                const float* gqy, const float* bqy,
                                const float* gky, const float* bky) {
    int w = (blockIdx.x * blockDim.x + threadIdx.x) >> 5;
    int lane = threadIdx.x & 31;
    int st = w / (MTOK * HEADS);
    int r  = w % (MTOK * HEADS);
    int t  = r / HEADS;
    int h  = r % HEADS;
    const __half* qkv = (st ? qkv1 : qkv0) + (long)t * QKVN + h * HD;
    int b = t >> 10, s = t & 1023;
    long obase = (((long)(b * HEADS + h)) * SFULL + st * SEQ + s) * HD;

    const float* gq = st ? gqy : gqx; const float* bq = st ? bqy : bqx;
    const float* gk = st ? gky : gkx; const float* bk = st ? bky : bkx;

    ln_row_h2(qkv,       Q  + obase, gq, bq, lane, SCF);
    ln_row_h2(qkv + DIM, Kb + obase, gk, bk, lane, 1.0f);
    *(half2*)(Vb + obase + 2 * lane) =
        *(const half2*)(qkv + 2 * DIM + 2 * lane);
}

// ---------------------------------------------------------------------------
// fp16 flash attention v4: 4 warps x 32 q, K-tiles of 64, 3-stage cp.async
// ring (one syncthreads/tile). QK^T restructured p-outer: each 16-key group
// does 8 MMAs -> ex2.f16x2 -> l-MMA inline, so MUFU of group p overlaps the
// HMMAs of group p+1 (scoreboard) instead of a serial exp block. Fixed
// softmax (Q pre-scaled), l via ones-MMA. Output [b, s, h, d] half.
// ---------------------------------------------------------------------------
#define AS 72
#define STG_H (64 * AS)
#define ATTN_SMEM (3 * 2 * STG_H * 2)        // 55296 bytes

__global__ void __launch_bounds__(128, 3) attn_h(
        const __half* __restrict__ Q, const __half* __restrict__ K,
        const __half* __restrict__ V, __half* __restrict__ O) {
    extern __shared__ __half smh[];
    __half* KsS = smh;               // [3][STG_H]
    __half* VsS = smh + 3 * STG_H;   // [3][STG_H]

    const int tid = threadIdx.x, lane = tid & 31, w = tid >> 5;
    const int gid = lane >> 2, tig = lane & 3;
    const int h = blockIdx.y, b = blockIdx.z;
    const long bh = ((long)(b * HEADS + h)) * (SFULL * HD);
    const int q0 = blockIdx.x * 128;

    const int arow = (lane & 7) + 8 * ((lane >> 3) & 1);
    const int acol = ((lane >> 4) & 1) * 8;
    const int brow = (lane & 7) + 8 * ((lane >> 4) & 1);
    const int bcol = ((lane >> 3) & 1) * 8;

    const uint32_t ks0 = cvta_s(KsS);
    const uint32_t vs0 = cvta_s(VsS);

    // Stage 128 Q rows through stage-0 buffers (rows 0-63 -> K, 64-127 -> V).
#pragma unroll
    for (int i = 0; i < 8; i++) {
        int s = i * 128 + tid;
        int r = s >> 3, c = (s & 7) * 8;
        uint4 v = *(const uint4*)(Q + bh + (long)(q0 + r) * HD + c);
        if (r < 64) *(uint4*)&KsS[r * AS + c] = v;
        else        *(uint4*)&VsS[(r - 64) * AS + c] = v;
    }
    __syncthreads();
    uint32_t qa[2][4][4];
#pragma unroll
    for (int rt = 0; rt < 2; rt++) {
        int qrow = w * 32 + rt * 16;
        uint32_t base = (qrow < 64)
            ? ks0 + (uint32_t)((qrow + arow) * AS) * 2
            : vs0 + (uint32_t)((qrow - 64 + arow) * AS) * 2;
#pragma unroll
        for (int kc = 0; kc < 4; kc++)
            ldsm4(qa[rt][kc], base + (kc * 16 + acol) * 2);
    }
    __syncthreads();

    float acc[2][8][4];
    float accl[2][4];
#pragma unroll
    for (int rt = 0; rt < 2; rt++) {
#pragma unroll
        for (int r = 0; r < 4; r++) accl[rt][r] = 0.f;
#pragma unroll
        for (int nt = 0; nt < 8; nt++)
#pragma unroll
            for (int r = 0; r < 4; r++) acc[rt][nt][r] = 0.f;
    }
    const uint32_t ONE2 = 0x3C003C00u;

    // cp.async staging slots
    int srow[4], scol[4];
#pragma unroll
    for (int i = 0; i < 4; i++) {
        int s = i * 128 + tid;
        srow[i] = s >> 3;
        scol[i] = (s & 7) * 8;
    }

    // Prologue: stage tiles 0 and 1 into stages 0, 1.
#pragma unroll
    for (int st = 0; st < 2; st++) {
#pragma unroll
        for (int i = 0; i < 4; i++) {
            uint32_t so = (uint32_t)(st * STG_H + srow[i] * AS + scol[i]) * 2;
            long go = (long)(st * 64 + srow[i]) * HD + scol[i];
            cp16(ks0 + so, K + bh + go);
            cp16(vs0 + so, V + bh + go);
        }
        CP_COMMIT();
    }

    const int NT = SFULL / 64;
    int cur = 0;
    for (int t = 0; t < NT; t++) {
        if (t + 2 < NT) { CP_WAIT(1); } else { CP_WAIT(0); }
        __syncthreads();

        if (t + 2 < NT) {
            int nst = cur + 2; if (nst >= 3) nst -= 3;
#pragma unroll
            for (int i = 0; i < 4; i++) {
                uint32_t so = (uint32_t)(nst * STG_H + srow[i] * AS + scol[i]) * 2;
                long go = (long)((t + 2) * 64 + srow[i]) * HD + scol[i];
                cp16(ks0 + so, K + bh + go);
                cp16(vs0 + so, V + bh + go);
            }
            CP_COMMIT();
        }

        const uint32_t kc_base = ks0 + (uint32_t)(cur * STG_H) * 2;
        const uint32_t vc_base = vs0 + (uint32_t)(cur * STG_H) * 2;

        // S = Q @ K^T, p-outer: per 16-key group do MMAs + exp + l-MMA
        // so each group's MUFU overlaps the next group's HMMAs.
        uint32_t pf[2][4][4];
#pragma unroll
        for (int rt = 0; rt < 2; rt++) {
#pragma unroll
            for (int p = 0; p < 4; p++) {
                float s0[4] = {0.f, 0.f, 0.f, 0.f};
                float s1[4] = {0.f, 0.f, 0.f, 0.f};
#pragma unroll
                for (int kc = 0; kc < 4; kc++) {
                    uint32_t kb[4];
                    ldsm4(kb, kc_base +
                        ((p * 16 + brow) * AS + kc * 16 + bcol) * 2);
                    mma_f16(s0, qa[rt][kc], kb[0], kb[1]);
                    mma_f16(s1, qa[rt][kc], kb[2], kb[3]);
                }
                pf[rt][p][0] = h2exp2(packh2(s0[0], s0[1]));
                pf[rt][p][1] = h2exp2(packh2(s0[2], s0[3]));
                pf[rt][p][2] = h2exp2(packh2(s1[0], s1[1]));
                pf[rt][p][3] = h2exp2(packh2(s1[2], s1[3]));
                mma_f16(accl[rt], pf[rt][p], ONE2, ONE2);
            }
        }

        // O += P @ V (V fragments shared across both row-tiles)
#pragma unroll
        for (int kc = 0; kc < 4; kc++) {
#pragma unroll
            for (int p = 0; p < 4; p++) {
                uint32_t vb[4];
                ldsm4t(vb, vc_base +
                    ((kc * 16 + arow) * AS + p * 16 + acol) * 2);
#pragma unroll
                for (int rt = 0; rt < 2; rt++) {
                    mma_f16(acc[rt][2 * p],     pf[rt][kc], vb[0], vb[1]);
                    mma_f16(acc[rt][2 * p + 1], pf[rt][kc], vb[2], vb[3]);
                }
            }
        }

        cur++; if (cur >= 3) cur = 0;
    }

    // Epilogue: l fully reduced in accl (ones-MMA); normalize & store.
#pragma unroll
    for (int rt = 0; rt < 2; rt++) {
        float inv0 = 1.0f / accl[rt][0];
        float inv1 = 1.0f / accl[rt][2];
        int sg = q0 + w * 32 + rt * 16 + gid;
        long ob0 = (((long)(b * SFULL + sg))     * HEADS + h) * HD;
        long ob1 = (((long)(b * SFULL + sg + 8)) * HEADS + h) * HD;
#pragma unroll
        for (int nt = 0; nt < 8; nt++) {
            int c = nt * 8 + 2 * tig;
            *(half2*)&O[ob0 + c] = __floats2half2_rn(acc[rt][nt][0] * inv0,
                                                     acc[rt][nt][1] * inv0);
            *(half2*)&O[ob1 + c] = __floats2half2_rn(acc[rt][nt][2] * inv1,
                                                     acc[rt][nt][3] * inv1);
        }
    }
}

// ---------------------------------------------------------------------------
// Launch
// ---------------------------------------------------------------------------
extern "C" void kernel_launch(void* const* d_in, const int* in_sizes, int n_in,
                              void* d_out, int out_size) {
    const float* x       = (const float*)d_in[0];
    const float* y       = (const float*)d_in[1];
    const float* Wqkv_x  = (const float*)d_in[2];
    const float* bqkv_x  = (const float*)d_in[3];
    const float* Wqkv_y  = (const float*)d_in[4];
    const float* bqkv_y  = (const float*)d_in[5];
    const float* Wproj_x = (const float*)d_in[6];
    const float* bproj_x = (const float*)d_in[7];
    const float* Wproj_y = (const float*)d_in[8];
    const float* bproj_y = (const float*)d_in[9];
    const float* gq_x    = (const float*)d_in[10];
    const float* bq_x    = (const float*)d_in[11];
    const float* gk_x    = (const float*)d_in[12];
    const float* bk_x    = (const float*)d_in[13];
    const float* gq_y    = (const float*)d_in[14];
    const float* bq_y    = (const float*)d_in[15];
    const float* gk_y    = (const float*)d_in[16];
    const float* bk_y    = (const float*)d_in[17];
    float* out = (float*)d_out;

    __half *qkv0, *qkv1, *xh, *yh, *wqx, *wqy, *wpx, *wpy, *Qh, *Kh, *Vh, *Oh;
    cudaGetSymbolAddress((void**)&qkv0, g_qkv0);
    cudaGetSymbolAddress((void**)&qkv1, g_qkv1);
    cudaGetSymbolAddress((void**)&xh,  g_xh);
    cudaGetSymbolAddress((void**)&yh,  g_yh);
    cudaGetSymbolAddress((void**)&wqx, g_wqx);
    cudaGetSymbolAddress((void**)&wqy, g_wqy);
    cudaGetSymbolAddress((void**)&wpx, g_wpx);
    cudaGetSymbolAddress((void**)&wpy, g_wpy);
    cudaGetSymbolAddress((void**)&Qh,  g_Qh);
    cudaGetSymbolAddress((void**)&Kh,  g_Kh);
    cudaGetSymbolAddress((void**)&Vh,  g_Vh);
    cudaGetSymbolAddress((void**)&Oh,  g_Oh);

    cudaFuncSetAttribute(attn_h,
                         cudaFuncAttributeMaxDynamicSharedMemorySize,
                         ATTN_SMEM);

    // Prep: convert all inputs/weights to fp16 in one launch
    cvt_all<<<NCVT / 256, 256>>>(x, y, Wqkv_x, Wqkv_y, Wproj_x, Wproj_y,
                                 xh, yh, wqx, wqy, wpx, wpy);

    // QKV projections for both streams (half output)
    gemm2_h<__half><<<dim3(QKVN / 128, MTOK / 128, 2), 256>>>(
        xh, yh, 1024L * DIM, wqx, wqy, bqkv_x, bqkv_y,
        qkv0, qkv1, QKVN, DIM);

    // LN(q,k) + split into half concat [b,h,2048,64]; Q pre-scaled
    ln_split_kernel<<<(2 * MTOK * HEADS) / 8, 256>>>(
        qkv0, qkv1, Qh, Kh, Vh,
        gq_x, bq_x, gk_x, bk_x, gq_y, bq_y, gk_y, bk_y);

    // Attention: 128 q per block, 3-stage cp.async ring
    attn_h<<<dim3(SFULL / 128, HEADS, BATCH), 128, ATTN_SMEM>>>(
        Qh, Kh, Vh, Oh);

    // Output projections for both streams (float output)
    gemm2_h<float><<<dim3(DIM / 128, MTOK / 128, 2), 256>>>(
        Oh, Oh + (long)SEQ * DIM, (long)SFULL * DIM, wpx, wpy,
        bproj_x, bproj_y, out, out + (long)MTOK * DIM, DIM, DIM);
}

// round 14
// speedup vs baseline: 1.0221x; 1.0221x over previous
#include <cuda_runtime.h>
#include <cuda_fp16.h>
#include <math.h>
#include <stdint.h>

// ---------------------------------------------------------------------------
// Problem constants
// ---------------------------------------------------------------------------
#define BATCH   4
#define SEQ     1024
#define DIM     768
#define HEADS   12
#define HD      64
#define SFULL   2048
#define MTOK    4096
#define QKVN    2304
#define BHSD    ((long)BATCH * HEADS * SFULL * HD)

// ---------------------------------------------------------------------------
// Scratch (__device__ globals; no allocation)
// ---------------------------------------------------------------------------
__device__ __half g_qkv0[(long)MTOK * QKVN];
__device__ __half g_qkv1[(long)MTOK * QKVN];
__device__ __half g_xh[(long)MTOK * DIM];
__device__ __half g_yh[(long)MTOK * DIM];
__device__ __half g_wqx[(long)QKVN * DIM];
__device__ __half g_wqy[(long)QKVN * DIM];
__device__ __half g_wpx[(long)DIM * DIM];
__device__ __half g_wpy[(long)DIM * DIM];
__device__ __half g_Qh[BHSD];
__device__ __half g_Kh[BHSD];
__device__ __half g_Vh[BHSD];
__device__ __half g_Oh[(long)BATCH * SFULL * DIM];

// ---------------------------------------------------------------------------
// mma / ldmatrix / cp.async helpers
// ---------------------------------------------------------------------------
__device__ __forceinline__ void mma_f16(float* d, const uint32_t* a,
                                        uint32_t b0, uint32_t b1) {
    asm volatile(
        "mma.sync.aligned.m16n8k16.row.col.f32.f16.f16.f32 "
        "{%0,%1,%2,%3}, {%4,%5,%6,%7}, {%8,%9}, {%0,%1,%2,%3};\n"
        : "+f"(d[0]), "+f"(d[1]), "+f"(d[2]), "+f"(d[3])
        : "r"(a[0]), "r"(a[1]), "r"(a[2]), "r"(a[3]), "r"(b0), "r"(b1));
}

__device__ __forceinline__ void ldsm4(uint32_t* r, uint32_t addr) {
    asm volatile(
        "ldmatrix.sync.aligned.m8n8.x4.shared.b16 {%0,%1,%2,%3}, [%4];"
        : "=r"(r[0]), "=r"(r[1]), "=r"(r[2]), "=r"(r[3]) : "r"(addr));
}

__device__ __forceinline__ void ldsm4t(uint32_t* r, uint32_t addr) {
    asm volatile(
        "ldmatrix.sync.aligned.m8n8.x4.trans.shared.b16 {%0,%1,%2,%3}, [%4];"
        : "=r"(r[0]), "=r"(r[1]), "=r"(r[2]), "=r"(r[3]) : "r"(addr));
}

__device__ __forceinline__ uint32_t cvta_s(const void* p) {
    return (uint32_t)__cvta_generic_to_shared(p);
}

__device__ __forceinline__ uint32_t packh2(float a, float b) {
    half2 h = __floats2half2_rn(a, b);
    return *(uint32_t*)&h;
}

__device__ __forceinline__ uint32_t h2exp2(uint32_t x) {
    uint32_t r;
    asm("ex2.approx.f16x2 %0, %1;" : "=r"(r) : "r"(x));
    return r;
}

__device__ __forceinline__ void cp16(uint32_t smem, const void* g) {
    asm volatile("cp.async.ca.shared.global [%0], [%1], 16;\n"
                 :: "r"(smem), "l"(g));
}
#define CP_COMMIT() asm volatile("cp.async.commit_group;\n")
#define CP_WAIT(n)  asm volatile("cp.async.wait_group %0;\n" :: "n"(n))

// Typed float2/half2 epilogue store
__device__ __forceinline__ void store2(float* C, long idx, float a, float b) {
    *(float2*)&C[idx] = make_float2(a, b);
}
__device__ __forceinline__ void store2(__half* C, long idx, float a, float b) {
    *(half2*)&C[idx] = __floats2half2_rn(a, b);
}

// ---------------------------------------------------------------------------
// Fused fp32 -> fp16 conversion for all 6 input tensors (one launch)
// ---------------------------------------------------------------------------
#define NXP (MTOK * DIM / 2)
#define NWP (QKVN * DIM / 2)
#define NPP (DIM * DIM / 2)
#define NCVT (2 * NXP + 2 * NWP + 2 * NPP)

__global__ void cvt_all(const float* __restrict__ x, const float* __restrict__ y,
                        const float* __restrict__ wqx, const float* __restrict__ wqy,
                        const float* __restrict__ wpx, const float* __restrict__ wpy,
                        __half* xh, __half* yh, __half* wqxh, __half* wqyh,
                        __half* wpxh, __half* wpyh) {
    int i = blockIdx.x * blockDim.x + threadIdx.x;
    const float* src; __half* dst; int off;
    if (i < NXP)                    { src = x;   dst = xh;   off = i; }
    else if (i < 2 * NXP)           { src = y;   dst = yh;   off = i - NXP; }
    else if (i < 2 * NXP + NWP)     { src = wqx; dst = wqxh; off = i - 2 * NXP; }
    else if (i < 2 * NXP + 2 * NWP) { src = wqy; dst = wqyh; off = i - 2 * NXP - NWP; }
    else if (i < 2 * NXP + 2 * NWP + NPP)
                                    { src = wpx; dst = wpxh; off = i - 2 * NXP - 2 * NWP; }
    else                            { src = wpy; dst = wpyh; off = i - 2 * NXP - 2 * NWP - NPP; }
    float2 v = ((const float2*)src)[off];
    ((half2*)dst)[off] = __floats2half2_rn(v.x, v.y);
}

// ---------------------------------------------------------------------------
// fp16 tensor-core GEMM, 3-stage cp.async ring (ONE syncthreads per k-step),
// paired x/y streams via blockIdx.z. C[M,N] = A @ B^T + bias (fp32 accum;
// TO = __half or float output). 256 thr = 8 warps (2M x 4N), tile 128x128,
// BK=32. Dynamic smem: 3 stages x (A + B) x 10KB = 60KB.
// ---------------------------------------------------------------------------
#define GKS 40
#define GST (128 * GKS)                 // halfs per matrix per stage
#define GEMM_SMEM (3 * 2 * GST * 2)     // 61440 bytes

template <typename TO>
__global__ void __launch_bounds__(256) gemm2_h(
        const __half* __restrict__ A0, const __half* __restrict__ A1,
        long a_bstride,
        const __half* __restrict__ B0, const __half* __restrict__ B1,
        const float* __restrict__ bias0, const float* __restrict__ bias1,
        TO* __restrict__ C0, TO* __restrict__ C1, int N, int K) {
    extern __shared__ __half gsm[];
    __half* As = gsm;                // [3][GST]
    __half* Bs = gsm + 3 * GST;      // [3][GST]

    const int z = blockIdx.z;
    const __half* A  = z ? A1 : A0;
    const __half* Bw = z ? B1 : B0;
    const float* bias = z ? bias1 : bias0;
    TO* C = z ? C1 : C0;

    const int tid = threadIdx.x, lane = tid & 31, w = tid >> 5;
    const int gid = lane >> 2, tig = lane & 3;
    const int bm = blockIdx.y, bn = blockIdx.x;
    const int wm = w & 1, wn = w >> 1;

    const int arow = (lane & 7) + 8 * ((lane >> 3) & 1);
    const int acol = ((lane >> 4) & 1) * 8;
    const int brow = (lane & 7) + 8 * ((lane >> 4) & 1);
    const int bcol = ((lane >> 3) & 1) * 8;

    int row[2], kg[2];
    const __half* ga[2];
    const __half* gb[2];
    uint32_t soff[2];
#pragma unroll
    for (int i = 0; i < 2; i++) {
        int s = i * 256 + tid;
        row[i] = s >> 2;
        kg[i]  = (s & 3) * 8;
        int m = bm * 128 + row[i];
        ga[i] = A + ((long)(m >> 10)) * a_bstride + (long)(m & 1023) * K + kg[i];
        gb[i] = Bw + (long)(bn * 128 + row[i]) * K + kg[i];
        soff[i] = (uint32_t)(row[i] * GKS + kg[i]) * 2;
    }

    const uint32_t as0 = cvta_s(As);
    const uint32_t bs0 = cvta_s(Bs);
    const int nsteps = K / 32;

    // Prologue: stage k-steps 0 and 1 into stages 0, 1.
#pragma unroll
    for (int st = 0; st < 2; st++) {
#pragma unroll
        for (int i = 0; i < 2; i++) {
            cp16(as0 + st * GST * 2 + soff[i], ga[i] + st * 32);
            cp16(bs0 + st * GST * 2 + soff[i], gb[i] + st * 32);
        }
        CP_COMMIT();
    }

    float acc[4][4][4];
#pragma unroll
    for (int mt = 0; mt < 4; mt++)
#pragma unroll
        for (int nt = 0; nt < 4; nt++)
#pragma unroll
            for (int r = 0; r < 4; r++) acc[mt][nt][r] = 0.f;

    int cur = 0;
    for (int kt = 0; kt < nsteps; kt++) {
        if (kt + 2 < nsteps) { CP_WAIT(1); } else { CP_WAIT(0); }
        __syncthreads();

        // Issue k-step kt+2 into stage (cur+2)%3 — tile kt-1's readers all
        // passed the sync above.
        if (kt + 2 < nsteps) {
            int nst = cur + 2; if (nst >= 3) nst -= 3;
#pragma unroll
            for (int i = 0; i < 2; i++) {
                cp16(as0 + nst * GST * 2 + soff[i], ga[i] + (kt + 2) * 32);
                cp16(bs0 + nst * GST * 2 + soff[i], gb[i] + (kt + 2) * 32);
            }
            CP_COMMIT();
        }

        const uint32_t asb = as0 + (uint32_t)(cur * GST) * 2;
        const uint32_t bsb = bs0 + (uint32_t)(cur * GST) * 2;
#pragma unroll
        for (int kc = 0; kc < 2; kc++) {
            uint32_t af[4][4], bf[2][4];
#pragma unroll
            for (int mt = 0; mt < 4; mt++)
                ldsm4(af[mt], asb +
                    ((wm * 64 + mt * 16 + arow) * GKS + kc * 16 + acol) * 2);
#pragma unroll
            for (int p = 0; p < 2; p++)
                ldsm4(bf[p], bsb +
                    ((wn * 32 + p * 16 + brow) * GKS + kc * 16 + bcol) * 2);
#pragma unroll
            for (int mt = 0; mt < 4; mt++)
#pragma unroll
                for (int p = 0; p < 2; p++) {
                    mma_f16(acc[mt][2 * p],     af[mt], bf[p][0], bf[p][1]);
                    mma_f16(acc[mt][2 * p + 1], af[mt], bf[p][2], bf[p][3]);
                }
        }

        cur++; if (cur >= 3) cur = 0;
    }

#pragma unroll
    for (int mt = 0; mt < 4; mt++) {
        int m0 = bm * 128 + wm * 64 + mt * 16 + gid;
#pragma unroll
        for (int nt = 0; nt < 4; nt++) {
            int n0 = bn * 128 + wn * 32 + nt * 8 + 2 * tig;
            float2 bb = *(const float2*)&bias[n0];
            store2(C, (long)m0 * N + n0,
                   acc[mt][nt][0] + bb.x, acc[mt][nt][1] + bb.y);
            store2(C, (long)(m0 + 8) * N + n0,
                   acc[mt][nt][2] + bb.x, acc[mt][nt][3] + bb.y);
        }
    }
}

// ---------------------------------------------------------------------------
// LayerNorm (q,k) + split into [b, h, 2048, 64] half layout.
// Q output pre-scaled by log2(e)/8 (softmax fold).
// ---------------------------------------------------------------------------
#define SCF 0.180336906f

__device__ __forceinline__ void ln_row_h2(const __half* __restrict__ x,
                                          __half* __restrict__ out,
                                          const float* __restrict__ g,
                                          const float* __restrict__ bb,
                                          int lane, float sc) {
    float2 xv = __half22float2(*(const half2*)(x + 2 * lane));
    float sum = xv.x + xv.y;
#pragma unroll
    for (int o = 16; o; o >>= 1) sum += __shfl_xor_sync(0xffffffffu, sum, o);
    float mu = sum * (1.0f / 64.0f);
    float d0 = xv.x - mu, d1 = xv.y - mu;
    float v = d0 * d0 + d1 * d1;
#pragma unroll
    for (int o = 16; o; o >>= 1) v += __shfl_xor_sync(0xffffffffu, v, o);
    float inv = rsqrtf(v * (1.0f / 64.0f) + 1e-5f);
    float2 gv = *(const float2*)(g + 2 * lane);
    float2 bv = *(const float2*)(bb + 2 * lane);
    float o0 = (d0 * inv * gv.x + bv.x) * sc;
    float o1 = (d1 * inv * gv.y + bv.y) * sc;
    *(half2*)(out + 2 * lane) = __floats2half2_rn(o0, o1);
}

__global__ void ln_split_kernel(const __half* __restrict__ qkv0,
                                const __half* __restrict__ qkv1,
                                __half* __restrict__ Q, __half* __restrict__ Kb,
                                __half* __restrict__ Vb,
                                const float* gqx, const float* bqx,
                                const float* gkx, const float* bkx,
                                const float* gqy, const float* bqy,
                                const float* gky, const float* bky) {
    int w = (blockIdx.x * blockDim.x + threadIdx.x) >> 5;
    int lane = threadIdx.x & 31;
    int st = w / (MTOK * HEADS);
    int r  = w % (MTOK * HEADS);
    int t  = r / HEADS;
    int h  = r % HEADS;
    const __half* qkv = (st ? qkv1 : qkv0) + (long)t * QKVN + h * HD;
    int b = t >> 10, s = t & 1023;
    long obase = (((long)(b * HEADS + h)) * SFULL + st * SEQ + s) * HD;

    const float* gq = st ? gqy : gqx; const float* bq = st ? bqy : bqx;
    const float* gk = st ? gky : gkx; const float* bk = st ? bky : bkx;

    ln_row_h2(qkv,       Q  + obase, gq, bq, lane, SCF);
    ln_row_h2(qkv + DIM, Kb + obase, gk, bk, lane, 1.0f);
    *(half2*)(Vb + obase + 2 * lane) =
        *(const half2*)(qkv + 2 * DIM + 2 * lane);
}

// ---------------------------------------------------------------------------
// fp16 flash attention v5: 4 warps x 32 q, K-tiles of 64, 3-stage cp.async
// ring (one syncthreads/tile). K fragments hoisted across both q row-tiles
// (16 LDSM for QK instead of 32). Fixed softmax (Q pre-scaled; P = exp2 via
// ex2.approx.f16x2), l via ones-MMA. Output [b, s, h, d] half.
// ---------------------------------------------------------------------------
#define AS 72
#define STG_H (64 * AS)
#define ATTN_SMEM (3 * 2 * STG_H * 2)        // 55296 bytes

__global__ void __launch_bounds__(128, 3) attn_h(
        const __half* __restrict__ Q, const __half* __restrict__ K,
        const __half* __restrict__ V, __half* __restrict__ O) {
    extern __shared__ __half smh[];
    __half* KsS = smh;               // [3][STG_H]
    __half* VsS = smh + 3 * STG_H;   // [3][STG_H]

    const int tid = threadIdx.x, lane = tid & 31, w = tid >> 5;
    const int gid = lane >> 2, tig = lane & 3;
    const int h = blockIdx.y, b = blockIdx.z;
    const long bh = ((long)(b * HEADS + h)) * (SFULL * HD);
    const int q0 = blockIdx.x * 128;

    const int arow = (lane & 7) + 8 * ((lane >> 3) & 1);
    const int acol = ((lane >> 4) & 1) * 8;
    const int brow = (lane & 7) + 8 * ((lane >> 4) & 1);
    const int bcol = ((lane >> 3) & 1) * 8;

    const uint32_t ks0 = cvta_s(KsS);
    const uint32_t vs0 = cvta_s(VsS);

    // Stage 128 Q rows through stage-0 buffers (rows 0-63 -> K, 64-127 -> V).
#pragma unroll
    for (int i = 0; i < 8; i++) {
        int s = i * 128 + tid;
        int r = s >> 3, c = (s & 7) * 8;
        uint4 v = *(const uint4*)(Q + bh + (long)(q0 + r) * HD + c);
        if (r < 64) *(uint4*)&KsS[r * AS + c] = v;
        else        *(uint4*)&VsS[(r - 64) * AS + c] = v;
    }
    __syncthreads();
    uint32_t qa[2][4][4];
#pragma unroll
    for (int rt = 0; rt < 2; rt++) {
        int qrow = w * 32 + rt * 16;
        uint32_t base = (qrow < 64)
            ? ks0 + (uint32_t)((qrow + arow) * AS) * 2
            : vs0 + (uint32_t)((qrow - 64 + arow) * AS) * 2;
#pragma unroll
        for (int kc = 0; kc < 4; kc++)
            ldsm4(qa[rt][kc], base + (kc * 16 + acol) * 2);
    }
    __syncthreads();

    float acc[2][8][4];
    float accl[2][4];
#pragma unroll
    for (int rt = 0; rt < 2; rt++) {
#pragma unroll
        for (int r = 0; r < 4; r++) accl[rt][r] = 0.f;
#pragma unroll
        for (int nt = 0; nt < 8; nt++)
#pragma unroll
            for (int r = 0; r < 4; r++) acc[rt][nt][r] = 0.f;
    }
    const uint32_t ONE2 = 0x3C003C00u;

    // cp.async staging slots
    int srow[4], scol[4];
#pragma unroll
    for (int i = 0; i < 4; i++) {
        int s = i * 128 + tid;
        srow[i] = s >> 3;
        scol[i] = (s & 7) * 8;
    }

    // Prologue: stage tiles 0 and 1 into stages 0, 1.
#pragma unroll
    for (int st = 0; st < 2; st++) {
#pragma unroll
        for (int i = 0; i < 4; i++) {
            uint32_t so = (uint32_t)(st * STG_H + srow[i] * AS + scol[i]) * 2;
            long go = (long)(st * 64 + srow[i]) * HD + scol[i];
            cp16(ks0 + so, K + bh + go);
            cp16(vs0 + so, V + bh + go);
        }
        CP_COMMIT();
    }

    const int NT = SFULL / 64;
    int cur = 0;
    for (int t = 0; t < NT; t++) {
        if (t + 2 < NT) { CP_WAIT(1); } else { CP_WAIT(0); }
        __syncthreads();

        if (t + 2 < NT) {
            int nst = cur + 2; if (nst >= 3) nst -= 3;
#pragma unroll
            for (int i = 0; i < 4; i++) {
                uint32_t so = (uint32_t)(nst * STG_H + srow[i] * AS + scol[i]) * 2;
                long go = (long)((t + 2) * 64 + srow[i]) * HD + scol[i];
                cp16(ks0 + so, K + bh + go);
                cp16(vs0 + so, V + bh + go);
            }
            CP_COMMIT();
        }

        const uint32_t kc_base = ks0 + (uint32_t)(cur * STG_H) * 2;
        const uint32_t vc_base = vs0 + (uint32_t)(cur * STG_H) * 2;

        // S = Q @ K^T, p-outer; K fragments loaded ONCE and shared across
        // both q row-tiles (halves QK LDSM count).
        uint32_t pf[2][4][4];
#pragma unroll
        for (int p = 0; p < 4; p++) {
            float s0[2][4] = {{0.f, 0.f, 0.f, 0.f}, {0.f, 0.f, 0.f, 0.f}};
            float s1[2][4] = {{0.f, 0.f, 0.f, 0.f}, {0.f, 0.f, 0.f, 0.f}};
#pragma unroll
            for (int kc = 0; kc < 4; kc++) {
                uint32_t kb[4];
                ldsm4(kb, kc_base +
                    ((p * 16 + brow) * AS + kc * 16 + bcol) * 2);
#pragma unroll
                for (int rt = 0; rt < 2; rt++) {
                    mma_f16(s0[rt], qa[rt][kc], kb[0], kb[1]);
                    mma_f16(s1[rt], qa[rt][kc], kb[2], kb[3]);
                }
            }
#pragma unroll
            for (int rt = 0; rt < 2; rt++) {
                pf[rt][p][0] = h2exp2(packh2(s0[rt][0], s0[rt][1]));
                pf[rt][p][1] = h2exp2(packh2(s0[rt][2], s0[rt][3]));
                pf[rt][p][2] = h2exp2(packh2(s1[rt][0], s1[rt][1]));
                pf[rt][p][3] = h2exp2(packh2(s1[rt][2], s1[rt][3]));
                mma_f16(accl[rt], pf[rt][p], ONE2, ONE2);
            }
        }

        // O += P @ V (V fragments shared across both row-tiles)
#pragma unroll
        for (int kc = 0; kc < 4; kc++) {
#pragma unroll
            for (int p = 0; p < 4; p++) {
                uint32_t vb[4];
                ldsm4t(vb, vc_base +
                    ((kc * 16 + arow) * AS + p * 16 + acol) * 2);
#pragma unroll
                for (int rt = 0; rt < 2; rt++) {
                    mma_f16(acc[rt][2 * p],     pf[rt][kc], vb[0], vb[1]);
                    mma_f16(acc[rt][2 * p + 1], pf[rt][kc], vb[2], vb[3]);
                }
            }
        }

        cur++; if (cur >= 3) cur = 0;
    }

    // Epilogue: l fully reduced in accl (ones-MMA); normalize & store.
#pragma unroll
    for (int rt = 0; rt < 2; rt++) {
        float inv0 = 1.0f / accl[rt][0];
        float inv1 = 1.0f / accl[rt][2];
        int sg = q0 + w * 32 + rt * 16 + gid;
        long ob0 = (((long)(b * SFULL + sg))     * HEADS + h) * HD;
        long ob1 = (((long)(b * SFULL + sg + 8)) * HEADS + h) * HD;
#pragma unroll
        for (int nt = 0; nt < 8; nt++) {
            int c = nt * 8 + 2 * tig;
            *(half2*)&O[ob0 + c] = __floats2half2_rn(acc[rt][nt][0] * inv0,
                                                     acc[rt][nt][1] * inv0);
            *(half2*)&O[ob1 + c] = __floats2half2_rn(acc[rt][nt][2] * inv1,
                                                     acc[rt][nt][3] * inv1);
        }
    }
}

// ---------------------------------------------------------------------------
// Launch
// ---------------------------------------------------------------------------
extern "C" void kernel_launch(void* const* d_in, const int* in_sizes, int n_in,
                              void* d_out, int out_size) {
    const float* x       = (const float*)d_in[0];
    const float* y       = (const float*)d_in[1];
    const float* Wqkv_x  = (const float*)d_in[2];
    const float* bqkv_x  = (const float*)d_in[3];
    const float* Wqkv_y  = (const float*)d_in[4];
    const float* bqkv_y  = (const float*)d_in[5];
    const float* Wproj_x = (const float*)d_in[6];
    const float* bproj_x = (const float*)d_in[7];
    const float* Wproj_y = (const float*)d_in[8];
    const float* bproj_y = (const float*)d_in[9];
    const float* gq_x    = (const float*)d_in[10];
    const float* bq_x    = (const float*)d_in[11];
    const float* gk_x    = (const float*)d_in[12];
    const float* bk_x    = (const float*)d_in[13];
    const float* gq_y    = (const float*)d_in[14];
    const float* bq_y    = (const float*)d_in[15];
    const float* gk_y    = (const float*)d_in[16];
    const float* bk_y    = (const float*)d_in[17];
    float* out = (float*)d_out;

    __half *qkv0, *qkv1, *xh, *yh, *wqx, *wqy, *wpx, *wpy, *Qh, *Kh, *Vh, *Oh;
    cudaGetSymbolAddress((void**)&qkv0, g_qkv0);
    cudaGetSymbolAddress((void**)&qkv1, g_qkv1);
    cudaGetSymbolAddress((void**)&xh,  g_xh);
    cudaGetSymbolAddress((void**)&yh,  g_yh);
    cudaGetSymbolAddress((void**)&wqx, g_wqx);
    cudaGetSymbolAddress((void**)&wqy, g_wqy);
    cudaGetSymbolAddress((void**)&wpx, g_wpx);
    cudaGetSymbolAddress((void**)&wpy, g_wpy);
    cudaGetSymbolAddress((void**)&Qh,  g_Qh);
    cudaGetSymbolAddress((void**)&Kh,  g_Kh);
    cudaGetSymbolAddress((void**)&Vh,  g_Vh);
    cudaGetSymbolAddress((void**)&Oh,  g_Oh);

    cudaFuncSetAttribute(attn_h,
                         cudaFuncAttributeMaxDynamicSharedMemorySize,
                         ATTN_SMEM);
    cudaFuncSetAttribute(gemm2_h<__half>,
                         cudaFuncAttributeMaxDynamicSharedMemorySize,
                         GEMM_SMEM);
    cudaFuncSetAttribute(gemm2_h<float>,
                         cudaFuncAttributeMaxDynamicSharedMemorySize,
                         GEMM_SMEM);

    // Prep: convert all inputs/weights to fp16 in one launch
    cvt_all<<<NCVT / 256, 256>>>(x, y, Wqkv_x, Wqkv_y, Wproj_x, Wproj_y,
                                 xh, yh, wqx, wqy, wpx, wpy);

    // QKV projections for both streams (half output)
    gemm2_h<__half><<<dim3(QKVN / 128, MTOK / 128, 2), 256, GEMM_SMEM>>>(
        xh, yh, 1024L * DIM, wqx, wqy, bqkv_x, bqkv_y,
        qkv0, qkv1, QKVN, DIM);

    // LN(q,k) + split into half concat [b,h,2048,64]; Q pre-scaled
    ln_split_kernel<<<(2 * MTOK * HEADS) / 8, 256>>>(
        qkv0, qkv1, Qh, Kh, Vh,
        gq_x, bq_x, gk_x, bk_x, gq_y, bq_y, gk_y, bk_y);

    // Attention: 128 q per block, 3-stage cp.async ring
    attn_h<<<dim3(SFULL / 128, HEADS, BATCH), 128, ATTN_SMEM>>>(
        Qh, Kh, Vh, Oh);

    // Output projections for both streams (float output)
    gemm2_h<float><<<dim3(DIM / 128, MTOK / 128, 2), 256, GEMM_SMEM>>>(
        Oh, Oh + (long)SEQ * DIM, (long)SFULL * DIM, wpx, wpy,
        bproj_x, bproj_y, out, out + (long)MTOK * DIM, DIM, DIM);
}

// round 16
// speedup vs baseline: 1.0281x; 1.0059x over previous
#include <cuda_runtime.h>
#include <cuda_fp16.h>
#include <math.h>
#include <stdint.h>

// ---------------------------------------------------------------------------
// Problem constants
// ---------------------------------------------------------------------------
#define BATCH   4
#define SEQ     1024
#define DIM     768
#define HEADS   12
#define HD      64
#define SFULL   2048
#define MTOK    4096
#define QKVN    2304
#define BHSD    ((long)BATCH * HEADS * SFULL * HD)

// ---------------------------------------------------------------------------
// Scratch (__device__ globals; no allocation)
// ---------------------------------------------------------------------------
__device__ __half g_qkv0[(long)MTOK * QKVN];
__device__ __half g_qkv1[(long)MTOK * QKVN];
__device__ __half g_xh[(long)MTOK * DIM];
__device__ __half g_yh[(long)MTOK * DIM];
__device__ __half g_wqx[(long)QKVN * DIM];
__device__ __half g_wqy[(long)QKVN * DIM];
__device__ __half g_wpx[(long)DIM * DIM];
__device__ __half g_wpy[(long)DIM * DIM];
__device__ __half g_Qh[BHSD];
__device__ __half g_Kh[BHSD];
__device__ __half g_Vh[BHSD];
__device__ __half g_Oh[(long)BATCH * SFULL * DIM];

// ---------------------------------------------------------------------------
// mma / ldmatrix / cp.async helpers
// ---------------------------------------------------------------------------
__device__ __forceinline__ void mma_f16(float* d, const uint32_t* a,
                                        uint32_t b0, uint32_t b1) {
    asm volatile(
        "mma.sync.aligned.m16n8k16.row.col.f32.f16.f16.f32 "
        "{%0,%1,%2,%3}, {%4,%5,%6,%7}, {%8,%9}, {%0,%1,%2,%3};\n"
        : "+f"(d[0]), "+f"(d[1]), "+f"(d[2]), "+f"(d[3])
        : "r"(a[0]), "r"(a[1]), "r"(a[2]), "r"(a[3]), "r"(b0), "r"(b1));
}

__device__ __forceinline__ void ldsm4(uint32_t* r, uint32_t addr) {
    asm volatile(
        "ldmatrix.sync.aligned.m8n8.x4.shared.b16 {%0,%1,%2,%3}, [%4];"
        : "=r"(r[0]), "=r"(r[1]), "=r"(r[2]), "=r"(r[3]) : "r"(addr));
}

__device__ __forceinline__ void ldsm4t(uint32_t* r, uint32_t addr) {
    asm volatile(
        "ldmatrix.sync.aligned.m8n8.x4.trans.shared.b16 {%0,%1,%2,%3}, [%4];"
        : "=r"(r[0]), "=r"(r[1]), "=r"(r[2]), "=r"(r[3]) : "r"(addr));
}

__device__ __forceinline__ uint32_t cvta_s(const void* p) {
    return (uint32_t)__cvta_generic_to_shared(p);
}

__device__ __forceinline__ uint32_t packh2(float a, float b) {
    half2 h = __floats2half2_rn(a, b);
    return *(uint32_t*)&h;
}

__device__ __forceinline__ uint32_t h2exp2(uint32_t x) {
    uint32_t r;
    asm("ex2.approx.f16x2 %0, %1;" : "=r"(r) : "r"(x));
    return r;
}

__device__ __forceinline__ void cp16(uint32_t smem, const void* g) {
    asm volatile("cp.async.ca.shared.global [%0], [%1], 16;\n"
                 :: "r"(smem), "l"(g));
}
#define CP_COMMIT() asm volatile("cp.async.commit_group;\n")
#define CP_WAIT(n)  asm volatile("cp.async.wait_group %0;\n" :: "n"(n))

// Typed float2/half2 epilogue store
__device__ __forceinline__ void store2(float* C, long idx, float a, float b) {
    *(float2*)&C[idx] = make_float2(a, b);
}
__device__ __forceinline__ void store2(__half* C, long idx, float a, float b) {
    *(half2*)&C[idx] = __floats2half2_rn(a, b);
}

// ---------------------------------------------------------------------------
// Fused fp32 -> fp16 conversion for all 6 input tensors (one launch)
// ---------------------------------------------------------------------------
#define NXP (MTOK * DIM / 2)
#define NWP (QKVN * DIM / 2)
#define NPP (DIM * DIM / 2)
#define NCVT (2 * NXP + 2 * NWP + 2 * NPP)

__global__ void cvt_all(const float* __restrict__ x, const float* __restrict__ y,
                        const float* __restrict__ wqx, const float* __restrict__ wqy,
                        const float* __restrict__ wpx, const float* __restrict__ wpy,
                        __half* xh, __half* yh, __half* wqxh, __half* wqyh,
                        __half* wpxh, __half* wpyh) {
    int i = blockIdx.x * blockDim.x + threadIdx.x;
    const float* src; __half* dst; int off;
    if (i < NXP)                    { src = x;   dst = xh;   off = i; }
    else if (i < 2 * NXP)           { src = y;   dst = yh;   off = i - NXP; }
    else if (i < 2 * NXP + NWP)     { src = wqx; dst = wqxh; off = i - 2 * NXP; }
    else if (i < 2 * NXP + 2 * NWP) { src = wqy; dst = wqyh; off = i - 2 * NXP - NWP; }
    else if (i < 2 * NXP + 2 * NWP + NPP)
                                    { src = wpx; dst = wpxh; off = i - 2 * NXP - 2 * NWP; }
    else                            { src = wpy; dst = wpyh; off = i - 2 * NXP - 2 * NWP - NPP; }
    float2 v = ((const float2*)src)[off];
    ((half2*)dst)[off] = __floats2half2_rn(v.x, v.y);
}

// ---------------------------------------------------------------------------
// fp16 tensor-core GEMM, BK=64 per stage, 3-stage cp.async ring (ONE
// syncthreads per k-step, 12 steps for K=768). Paired x/y via blockIdx.z.
// C[M,N] = A @ B^T + bias (fp32 accum; TO = __half or float output).
// 256 thr = 8 warps (2M x 4N, 64x32/warp), tile 128x128.
// Stage = 128 rows x 72-half stride = 18432B/matrix; total smem 110592B.
// ---------------------------------------------------------------------------
#define GKS 72                            // half stride per row (64 + 8 pad)
#define GST (128 * GKS)                   // halfs per matrix per stage
#define GEMM_SMEM (3 * 2 * GST * 2)       // 110592 bytes

template <typename TO>
__global__ void __launch_bounds__(256) gemm2_h(
        const __half* __restrict__ A0, const __half* __restrict__ A1,
        long a_bstride,
        const __half* __restrict__ B0, const __half* __restrict__ B1,
        const float* __restrict__ bias0, const float* __restrict__ bias1,
        TO* __restrict__ C0, TO* __restrict__ C1, int N, int K) {
    extern __shared__ __half gsm[];
    __half* As = gsm;                // [3][GST]
    __half* Bs = gsm + 3 * GST;      // [3][GST]

    const int z = blockIdx.z;
    const __half* A  = z ? A1 : A0;
    const __half* Bw = z ? B1 : B0;
    const float* bias = z ? bias1 : bias0;
    TO* C = z ? C1 : C0;

    const int tid = threadIdx.x, lane = tid & 31, w = tid >> 5;
    const int gid = lane >> 2, tig = lane & 3;
    const int bm = blockIdx.y, bn = blockIdx.x;
    const int wm = w & 1, wn = w >> 1;

    const int arow = (lane & 7) + 8 * ((lane >> 3) & 1);
    const int acol = ((lane >> 4) & 1) * 8;
    const int brow = (lane & 7) + 8 * ((lane >> 4) & 1);
    const int bcol = ((lane >> 3) & 1) * 8;

    // Staging slots: 4 chunks of 16B per matrix per thread per step
    // (128 rows x 64 half = 1024 chunks / 256 threads).
    int row[4], kg[4];
    const __half* ga[4];
    const __half* gb[4];
    uint32_t soff[4];
#pragma unroll
    for (int i = 0; i < 4; i++) {
        int s = i * 256 + tid;
        row[i] = s >> 3;             // 8 chunks per 64-half row
        kg[i]  = (s & 7) * 8;
        int m = bm * 128 + row[i];
        ga[i] = A + ((long)(m >> 10)) * a_bstride + (long)(m & 1023) * K + kg[i];
        gb[i] = Bw + (long)(bn * 128 + row[i]) * K + kg[i];
        soff[i] = (uint32_t)(row[i] * GKS + kg[i]) * 2;
    }

    const uint32_t as0 = cvta_s(As);
    const uint32_t bs0 = cvta_s(Bs);
    const int nsteps = K / 64;       // 12

    // Prologue: stage k-steps 0 and 1 into stages 0, 1.
#pragma unroll
    for (int st = 0; st < 2; st++) {
#pragma unroll
        for (int i = 0; i < 4; i++) {
            cp16(as0 + st * GST * 2 + soff[i], ga[i] + st * 64);
            cp16(bs0 + st * GST * 2 + soff[i], gb[i] + st * 64);
        }
        CP_COMMIT();
    }

    float acc[4][4][4];
#pragma unroll
    for (int mt = 0; mt < 4; mt++)
#pragma unroll
        for (int nt = 0; nt < 4; nt++)
#pragma unroll
            for (int r = 0; r < 4; r++) acc[mt][nt][r] = 0.f;

    int cur = 0;
    for (int kt = 0; kt < nsteps; kt++) {
        if (kt + 2 < nsteps) { CP_WAIT(1); } else { CP_WAIT(0); }
        __syncthreads();

        // Issue k-step kt+2 into stage (cur+2)%3.
        if (kt + 2 < nsteps) {
            int nst = cur + 2; if (nst >= 3) nst -= 3;
#pragma unroll
            for (int i = 0; i < 4; i++) {
                cp16(as0 + nst * GST * 2 + soff[i], ga[i] + (kt + 2) * 64);
                cp16(bs0 + nst * GST * 2 + soff[i], gb[i] + (kt + 2) * 64);
            }
            CP_COMMIT();
        }

        const uint32_t asb = as0 + (uint32_t)(cur * GST) * 2;
        const uint32_t bsb = bs0 + (uint32_t)(cur * GST) * 2;
#pragma unroll
        for (int kc = 0; kc < 4; kc++) {
            uint32_t af[4][4], bf[2][4];
#pragma unroll
            for (int mt = 0; mt < 4; mt++)
                ldsm4(af[mt], asb +
                    ((wm * 64 + mt * 16 + arow) * GKS + kc * 16 + acol) * 2);
#pragma unroll
            for (int p = 0; p < 2; p++)
                ldsm4(bf[p], bsb +
                    ((wn * 32 + p * 16 + brow) * GKS + kc * 16 + bcol) * 2);
#pragma unroll
            for (int mt = 0; mt < 4; mt++)
#pragma unroll
                for (int p = 0; p < 2; p++) {
                    mma_f16(acc[mt][2 * p],     af[mt], bf[p][0], bf[p][1]);
                    mma_f16(acc[mt][2 * p + 1], af[mt], bf[p][2], bf[p][3]);
                }
        }

        cur++; if (cur >= 3) cur = 0;
    }

#pragma unroll
    for (int mt = 0; mt < 4; mt++) {
        int m0 = bm * 128 + wm * 64 + mt * 16 + gid;
#pragma unroll
        for (int nt = 0; nt < 4; nt++) {
            int n0 = bn * 128 + wn * 32 + nt * 8 + 2 * tig;
            float2 bb = *(const float2*)&bias[n0];
            store2(C, (long)m0 * N + n0,
                   acc[mt][nt][0] + bb.x, acc[mt][nt][1] + bb.y);
            store2(C, (long)(m0 + 8) * N + n0,
                   acc[mt][nt][2] + bb.x, acc[mt][nt][3] + bb.y);
        }
    }
}

// ---------------------------------------------------------------------------
// LayerNorm (q,k) + split into [b, h, 2048, 64] half layout.
// Q output pre-scaled by log2(e)/8 (softmax fold).
// ---------------------------------------------------------------------------
#define SCF 0.180336906f

__device__ __forceinline__ void ln_row_h2(const __half* __restrict__ x,
                                          __half* __restrict__ out,
                                          const float* __restrict__ g,
                                          const float* __restrict__ bb,
                                          int lane, float sc) {
    float2 xv = __half22float2(*(const half2*)(x + 2 * lane));
    float sum = xv.x + xv.y;
#pragma unroll
    for (int o = 16; o; o >>= 1) sum += __shfl_xor_sync(0xffffffffu, sum, o);
    float mu = sum * (1.0f / 64.0f);
    float d0 = xv.x - mu, d1 = xv.y - mu;
    float v = d0 * d0 + d1 * d1;
#pragma unroll
    for (int o = 16; o; o >>= 1) v += __shfl_xor_sync(0xffffffffu, v, o);
    float inv = rsqrtf(v * (1.0f / 64.0f) + 1e-5f);
    float2 gv = *(const float2*)(g + 2 * lane);
    float2 bv = *(const float2*)(bb + 2 * lane);
    float o0 = (d0 * inv * gv.x + bv.x) * sc;
    float o1 = (d1 * inv * gv.y + bv.y) * sc;
    *(half2*)(out + 2 * lane) = __floats2half2_rn(o0, o1);
}

__global__ void ln_split_kernel(const __half* __restrict__ qkv0,
                                const __half* __restrict__ qkv1,
                                __half* __restrict__ Q, __half* __restrict__ Kb,
                                __half* __restrict__ Vb,
                                const float* gqx, const float* bqx,
                                const float* gkx, const float* bkx,
                                const float* gqy, const float* bqy,
                                const float* gky, const float* bky) {
    int w = (blockIdx.x * blockDim.x + threadIdx.x) >> 5;
    int lane = threadIdx.x & 31;
    int st = w / (MTOK * HEADS);
    int r  = w % (MTOK * HEADS);
    int t  = r / HEADS;
    int h  = r % HEADS;
    const __half* qkv = (st ? qkv1 : qkv0) + (long)t * QKVN + h * HD;
    int b = t >> 10, s = t & 1023;
    long obase = (((long)(b * HEADS + h)) * SFULL + st * SEQ + s) * HD;

    const float* gq = st ? gqy : gqx; const float* bq = st ? bqy : bqx;
    const float* gk = st ? gky : gkx; const float* bk = st ? bky : bkx;

    ln_row_h2(qkv,       Q  + obase, gq, bq, lane, SCF);
    ln_row_h2(qkv + DIM, Kb + obase, gk, bk, lane, 1.0f);
    *(half2*)(Vb + obase + 2 * lane) =
        *(const half2*)(qkv + 2 * DIM + 2 * lane);
}

// ---------------------------------------------------------------------------
// fp16 flash attention (unchanged from R14): 4 warps x 32 q, K-tiles of 64,
// 3-stage cp.async ring, K frags shared across q row-tiles, fixed softmax,
// l via ones-MMA. Output [b, s, h, d] half.
// ---------------------------------------------------------------------------
#define AS 72
#define STG_H (64 * AS)
#define ATTN_SMEM (3 * 2 * STG_H * 2)

__global__ void __launch_bounds__(128, 3) attn_h(
        const __half* __restrict__ Q, const __half* __restrict__ K,
        const __half* __restrict__ V, __half* __restrict__ O) {
    extern __shared__ __half smh[];
    __half* KsS = smh;
    __half* VsS = smh + 3 * STG_H;

    const int tid = threadIdx.x, lane = tid & 31, w = tid >> 5;
    const int gid = lane >> 2, tig = lane & 3;
    const int h = blockIdx.y, b = blockIdx.z;
    const long bh = ((long)(b * HEADS + h)) * (SFULL * HD);
    const int q0 = blockIdx.x * 128;

    const int arow = (lane & 7) + 8 * ((lane >> 3) & 1);
    const int acol = ((lane >> 4) & 1) * 8;
    const int brow = (lane & 7) + 8 * ((lane >> 4) & 1);
    const int bcol = ((lane >> 3) & 1) * 8;

    const uint32_t ks0 = cvta_s(KsS);
    const uint32_t vs0 = cvta_s(VsS);

#pragma unroll
    for (int i = 0; i < 8; i++) {
        int s = i * 128 + tid;
        int r = s >> 3, c = (s & 7) * 8;
        uint4 v = *(const uint4*)(Q + bh + (long)(q0 + r) * HD + c);
        if (r < 64) *(uint4*)&KsS[r * AS + c] = v;
        else        *(uint4*)&VsS[(r - 64) * AS + c] = v;
    }
    __syncthreads();
    uint32_t qa[2][4][4];
#pragma unroll
    for (int rt = 0; rt < 2; rt++) {
        int qrow = w * 32 + rt * 16;
        uint32_t basea = (qrow < 64)
            ? ks0 + (uint32_t)((qrow + arow) * AS) * 2
            : vs0 + (uint32_t)((qrow - 64 + arow) * AS) * 2;
#pragma unroll
        for (int kc = 0; kc < 4; kc++)
            ldsm4(qa[rt][kc], basea + (kc * 16 + acol) * 2);
    }
    __syncthreads();

    float acc[2][8][4];
    float accl[2][4];
#pragma unroll
    for (int rt = 0; rt < 2; rt++) {
#pragma unroll
        for (int r = 0; r < 4; r++) accl[rt][r] = 0.f;
#pragma unroll
        for (int nt = 0; nt < 8; nt++)
#pragma unroll
            for (int r = 0; r < 4; r++) acc[rt][nt][r] = 0.f;
    }
    const uint32_t ONE2 = 0x3C003C00u;

    int srow[4], scol[4];
#pragma unroll
    for (int i = 0; i < 4; i++) {
        int s = i * 128 + tid;
        srow[i] = s >> 3;
        scol[i] = (s & 7) * 8;
    }

#pragma unroll
    for (int st = 0; st < 2; st++) {
#pragma unroll
        for (int i = 0; i < 4; i++) {
            uint32_t so = (uint32_t)(st * STG_H + srow[i] * AS + scol[i]) * 2;
            long go = (long)(st * 64 + srow[i]) * HD + scol[i];
            cp16(ks0 + so, K + bh + go);
            cp16(vs0 + so, V + bh + go);
        }
        CP_COMMIT();
    }

    const int NT = SFULL / 64;
    int cur = 0;
    for (int t = 0; t < NT; t++) {
        if (t + 2 < NT) { CP_WAIT(1); } else { CP_WAIT(0); }
        __syncthreads();

        if (t + 2 < NT) {
            int nst = cur + 2; if (nst >= 3) nst -= 3;
#pragma unroll
            for (int i = 0; i < 4; i++) {
                uint32_t so = (uint32_t)(nst * STG_H + srow[i] * AS + scol[i]) * 2;
                long go = (long)((t + 2) * 64 + srow[i]) * HD + scol[i];
                cp16(ks0 + so, K + bh + go);
                cp16(vs0 + so, V + bh + go);
            }
            CP_COMMIT();
        }

        const uint32_t kc_base = ks0 + (uint32_t)(cur * STG_H) * 2;
        const uint32_t vc_base = vs0 + (uint32_t)(cur * STG_H) * 2;

        uint32_t pf[2][4][4];
#pragma unroll
        for (int p = 0; p < 4; p++) {
            float s0[2][4] = {{0.f, 0.f, 0.f, 0.f}, {0.f, 0.f, 0.f, 0.f}};
            float s1[2][4] = {{0.f, 0.f, 0.f, 0.f}, {0.f, 0.f, 0.f, 0.f}};
#pragma unroll
            for (int kc = 0; kc < 4; kc++) {
                uint32_t kb[4];
                ldsm4(kb, kc_base +
                    ((p * 16 + brow) * AS + kc * 16 + bcol) * 2);
#pragma unroll
                for (int rt = 0; rt < 2; rt++) {
                    mma_f16(s0[rt], qa[rt][kc], kb[0], kb[1]);
                    mma_f16(s1[rt], qa[rt][kc], kb[2], kb[3]);
                }
            }
#pragma unroll
            for (int rt = 0; rt < 2; rt++) {
                pf[rt][p][0] = h2exp2(packh2(s0[rt][0], s0[rt][1]));
                pf[rt][p][1] = h2exp2(packh2(s0[rt][2], s0[rt][3]));
                pf[rt][p][2] = h2exp2(packh2(s1[rt][0], s1[rt][1]));
                pf[rt][p][3] = h2exp2(packh2(s1[rt][2], s1[rt][3]));
                mma_f16(accl[rt], pf[rt][p], ONE2, ONE2);
            }
        }

#pragma unroll
        for (int kc = 0; kc < 4; kc++) {
#pragma unroll
            for (int p = 0; p < 4; p++) {
                uint32_t vb[4];
                ldsm4t(vb, vc_base +
                    ((kc * 16 + arow) * AS + p * 16 + acol) * 2);
#pragma unroll
                for (int rt = 0; rt < 2; rt++) {
                    mma_f16(acc[rt][2 * p],     pf[rt][kc], vb[0], vb[1]);
                    mma_f16(acc[rt][2 * p + 1], pf[rt][kc], vb[2], vb[3]);
                }
            }
        }

        cur++; if (cur >= 3) cur = 0;
    }

#pragma unroll
    for (int rt = 0; rt < 2; rt++) {
        float inv0 = 1.0f / accl[rt][0];
        float inv1 = 1.0f / accl[rt][2];
        int sg = q0 + w * 32 + rt * 16 + gid;
        long ob0 = (((long)(b * SFULL + sg))     * HEADS + h) * HD;
        long ob1 = (((long)(b * SFULL + sg + 8)) * HEADS + h) * HD;
#pragma unroll
        for (int nt = 0; nt < 8; nt++) {
            int c = nt * 8 + 2 * tig;
            *(half2*)&O[ob0 + c] = __floats2half2_rn(acc[rt][nt][0] * inv0,
                                                     acc[rt][nt][1] * inv0);
            *(half2*)&O[ob1 + c] = __floats2half2_rn(acc[rt][nt][2] * inv1,
                                                     acc[rt][nt][3] * inv1);
        }
    }
}

// ---------------------------------------------------------------------------
// Launch
// ---------------------------------------------------------------------------
extern "C" void kernel_launch(void* const* d_in, const int* in_sizes, int n_in,
                              void* d_out, int out_size) {
    const float* x       = (const float*)d_in[0];
    const float* y       = (const float*)d_in[1];
    const float* Wqkv_x  = (const float*)d_in[2];
    const float* bqkv_x  = (const float*)d_in[3];
    const float* Wqkv_y  = (const float*)d_in[4];
    const float* bqkv_y  = (const float*)d_in[5];
    const float* Wproj_x = (const float*)d_in[6];
    const float* bproj_x = (const float*)d_in[7];
    const float* Wproj_y = (const float*)d_in[8];
    const float* bproj_y = (const float*)d_in[9];
    const float* gq_x    = (const float*)d_in[10];
    const float* bq_x    = (const float*)d_in[11];
    const float* gk_x    = (const float*)d_in[12];
    const float* bk_x    = (const float*)d_in[13];
    const float* gq_y    = (const float*)d_in[14];
    const float* bq_y    = (const float*)d_in[15];
    const float* gk_y    = (const float*)d_in[16];
    const float* bk_y    = (const float*)d_in[17];
    float* out = (float*)d_out;

    __half *qkv0, *qkv1, *xh, *yh, *wqx, *wqy, *wpx, *wpy, *Qh, *Kh, *Vh, *Oh;
    cudaGetSymbolAddress((void**)&qkv0, g_qkv0);
    cudaGetSymbolAddress((void**)&qkv1, g_qkv1);
    cudaGetSymbolAddress((void**)&xh,  g_xh);
    cudaGetSymbolAddress((void**)&yh,  g_yh);
    cudaGetSymbolAddress((void**)&wqx, g_wqx);
    cudaGetSymbolAddress((void**)&wqy, g_wqy);
    cudaGetSymbolAddress((void**)&wpx, g_wpx);
    cudaGetSymbolAddress((void**)&wpy, g_wpy);
    cudaGetSymbolAddress((void**)&Qh,  g_Qh);
    cudaGetSymbolAddress((void**)&Kh,  g_Kh);
    cudaGetSymbolAddress((void**)&Vh,  g_Vh);
    cudaGetSymbolAddress((void**)&Oh,  g_Oh);

    cudaFuncSetAttribute(attn_h,
                         cudaFuncAttributeMaxDynamicSharedMemorySize,
                         ATTN_SMEM);
    cudaFuncSetAttribute(gemm2_h<__half>,
                         cudaFuncAttributeMaxDynamicSharedMemorySize,
                         GEMM_SMEM);
    cudaFuncSetAttribute(gemm2_h<float>,
                         cudaFuncAttributeMaxDynamicSharedMemorySize,
                         GEMM_SMEM);

    // Prep: convert all inputs/weights to fp16 in one launch
    cvt_all<<<NCVT / 256, 256>>>(x, y, Wqkv_x, Wqkv_y, Wproj_x, Wproj_y,
                                 xh, yh, wqx, wqy, wpx, wpy);

    // QKV projections for both streams (half output)
    gemm2_h<__half><<<dim3(QKVN / 128, MTOK / 128, 2), 256, GEMM_SMEM>>>(
        xh, yh, 1024L * DIM, wqx, wqy, bqkv_x, bqkv_y,
        qkv0, qkv1, QKVN, DIM);

    // LN(q,k) + split into half concat [b,h,2048,64]; Q pre-scaled
    ln_split_kernel<<<(2 * MTOK * HEADS) / 8, 256>>>(
        qkv0, qkv1, Qh, Kh, Vh,
        gq_x, bq_x, gk_x, bk_x, gq_y, bq_y, gk_y, bk_y);

    // Attention: 128 q per block, 3-stage cp.async ring
    attn_h<<<dim3(SFULL / 128, HEADS, BATCH), 128, ATTN_SMEM>>>(
        Qh, Kh, Vh, Oh);

    // Output projections for both streams (float output)
    gemm2_h<float><<<dim3(DIM / 128, MTOK / 128, 2), 256, GEMM_SMEM>>>(
        Oh, Oh + (long)SEQ * DIM, (long)SFULL * DIM, wpx, wpy,
        bproj_x, bproj_y, out, out + (long)MTOK * DIM, DIM, DIM);
}

// round 17
// speedup vs baseline: 1.0864x; 1.0567x over previous
#include <cuda_runtime.h>
#include <cuda_fp16.h>
#include <math.h>
#include <stdint.h>

// ---------------------------------------------------------------------------
// Problem constants
// ---------------------------------------------------------------------------
#define BATCH   4
#define SEQ     1024
#define DIM     768
#define HEADS   12
#define HD      64
#define SFULL   2048
#define MTOK    4096
#define QKVN    2304
#define BHSD    ((long)BATCH * HEADS * SFULL * HD)

// ---------------------------------------------------------------------------
// Scratch (__device__ globals; no allocation)
// ---------------------------------------------------------------------------
__device__ __half g_xh[(long)MTOK * DIM];
__device__ __half g_yh[(long)MTOK * DIM];
__device__ __half g_wqx[(long)QKVN * DIM];
__device__ __half g_wqy[(long)QKVN * DIM];
__device__ __half g_wpx[(long)DIM * DIM];
__device__ __half g_wpy[(long)DIM * DIM];
__device__ __half g_Qh[BHSD];
__device__ __half g_Kh[BHSD];
__device__ __half g_Vh[BHSD];
__device__ __half g_Oh[(long)BATCH * SFULL * DIM];

// ---------------------------------------------------------------------------
// mma / ldmatrix / cp.async helpers
// ---------------------------------------------------------------------------
__device__ __forceinline__ void mma_f16(float* d, const uint32_t* a,
                                        uint32_t b0, uint32_t b1) {
    asm volatile(
        "mma.sync.aligned.m16n8k16.row.col.f32.f16.f16.f32 "
        "{%0,%1,%2,%3}, {%4,%5,%6,%7}, {%8,%9}, {%0,%1,%2,%3};\n"
        : "+f"(d[0]), "+f"(d[1]), "+f"(d[2]), "+f"(d[3])
        : "r"(a[0]), "r"(a[1]), "r"(a[2]), "r"(a[3]), "r"(b0), "r"(b1));
}

__device__ __forceinline__ void ldsm4(uint32_t* r, uint32_t addr) {
    asm volatile(
        "ldmatrix.sync.aligned.m8n8.x4.shared.b16 {%0,%1,%2,%3}, [%4];"
        : "=r"(r[0]), "=r"(r[1]), "=r"(r[2]), "=r"(r[3]) : "r"(addr));
}

__device__ __forceinline__ void ldsm4t(uint32_t* r, uint32_t addr) {
    asm volatile(
        "ldmatrix.sync.aligned.m8n8.x4.trans.shared.b16 {%0,%1,%2,%3}, [%4];"
        : "=r"(r[0]), "=r"(r[1]), "=r"(r[2]), "=r"(r[3]) : "r"(addr));
}

__device__ __forceinline__ uint32_t cvta_s(const void* p) {
    return (uint32_t)__cvta_generic_to_shared(p);
}

__device__ __forceinline__ uint32_t packh2(float a, float b) {
    half2 h = __floats2half2_rn(a, b);
    return *(uint32_t*)&h;
}

__device__ __forceinline__ uint32_t h2exp2(uint32_t x) {
    uint32_t r;
    asm("ex2.approx.f16x2 %0, %1;" : "=r"(r) : "r"(x));
    return r;
}

__device__ __forceinline__ void cp16(uint32_t smem, const void* g) {
    asm volatile("cp.async.ca.shared.global [%0], [%1], 16;\n"
                 :: "r"(smem), "l"(g));
}
#define CP_COMMIT() asm volatile("cp.async.commit_group;\n")
#define CP_WAIT(n)  asm volatile("cp.async.wait_group %0;\n" :: "n"(n))

__device__ __forceinline__ void store2(float* C, long idx, float a, float b) {
    *(float2*)&C[idx] = make_float2(a, b);
}
__device__ __forceinline__ void store2(__half* C, long idx, float a, float b) {
    *(half2*)&C[idx] = __floats2half2_rn(a, b);
}

#define SCF 0.180336906f   // log2(e)/8

// ---------------------------------------------------------------------------
// Fused fp32 -> fp16 conversion for all 6 input tensors (one launch)
// ---------------------------------------------------------------------------
#define NXP (MTOK * DIM / 2)
#define NWP (QKVN * DIM / 2)
#define NPP (DIM * DIM / 2)
#define NCVT (2 * NXP + 2 * NWP + 2 * NPP)

__global__ void cvt_all(const float* __restrict__ x, const float* __restrict__ y,
                        const float* __restrict__ wqx, const float* __restrict__ wqy,
                        const float* __restrict__ wpx, const float* __restrict__ wpy,
                        __half* xh, __half* yh, __half* wqxh, __half* wqyh,
                        __half* wpxh, __half* wpyh) {
    int i = blockIdx.x * blockDim.x + threadIdx.x;
    const float* src; __half* dst; int off;
    if (i < NXP)                    { src = x;   dst = xh;   off = i; }
    else if (i < 2 * NXP)           { src = y;   dst = yh;   off = i - NXP; }
    else if (i < 2 * NXP + NWP)     { src = wqx; dst = wqxh; off = i - 2 * NXP; }
    else if (i < 2 * NXP + 2 * NWP) { src = wqy; dst = wqyh; off = i - 2 * NXP - NWP; }
    else if (i < 2 * NXP + 2 * NWP + NPP)
                                    { src = wpx; dst = wpxh; off = i - 2 * NXP - 2 * NWP; }
    else                            { src = wpy; dst = wpyh; off = i - 2 * NXP - 2 * NWP - NPP; }
    float2 v = ((const float2*)src)[off];
    ((half2*)dst)[off] = __floats2half2_rn(v.x, v.y);
}

// ---------------------------------------------------------------------------
// GEMM common: BK=64 per stage, 3-stage cp.async ring, 256 thr = 8 warps
// (2M x 4N, 64x32 per warp), tile 128x128.
// ---------------------------------------------------------------------------
#define GKS 72                            // half stride per row (64 + 8 pad)
#define GST (128 * GKS)                   // halfs per matrix per stage
#define GEMM_SMEM (3 * 2 * GST * 2)       // 110592 bytes

// ---------------------------------------------------------------------------
// QKV GEMM with fused bias + per-head LayerNorm epilogue.
// Tile cols 128 = exactly 2 heads of q, k, or v (sec = bn/6).
// Writes LN'd q (pre-scaled log2e/8) / LN'd k / biased v directly into the
// [b, h, 2048, 64] half concat layout. Paired x/y streams via blockIdx.z.
// ---------------------------------------------------------------------------
__global__ void __launch_bounds__(256) gemm_qkv_ln(
        const __half* __restrict__ A0, const __half* __restrict__ A1,
        const __half* __restrict__ B0, const __half* __restrict__ B1,
        const float* __restrict__ bias0, const float* __restrict__ bias1,
        __half* __restrict__ Qh, __half* __restrict__ Kh,
        __half* __restrict__ Vh,
        const float* gqx, const float* bqx, const float* gkx, const float* bkx,
        const float* gqy, const float* bqy, const float* gky, const float* bky) {
    extern __shared__ __half gsm[];
    __half* As = gsm;
    __half* Bs = gsm + 3 * GST;

    const int z = blockIdx.z;
    const __half* A  = z ? A1 : A0;
    const __half* Bw = z ? B1 : B0;
    const float* bias = z ? bias1 : bias0;
    const int K = DIM;

    const int tid = threadIdx.x, lane = tid & 31, w = tid >> 5;
    const int gid = lane >> 2, tig = lane & 3;
    const int bm = blockIdx.y, bn = blockIdx.x;
    const int wm = w & 1, wn = w >> 1;

    const int arow = (lane & 7) + 8 * ((lane >> 3) & 1);
    const int acol = ((lane >> 4) & 1) * 8;
    const int brow = (lane & 7) + 8 * ((lane >> 4) & 1);
    const int bcol = ((lane >> 3) & 1) * 8;

    int row[4], kg[4];
    const __half* ga[4];
    const __half* gb[4];
    uint32_t soff[4];
#pragma unroll
    for (int i = 0; i < 4; i++) {
        int s = i * 256 + tid;
        row[i] = s >> 3;
        kg[i]  = (s & 7) * 8;
        int m = bm * 128 + row[i];
        ga[i] = A + (long)m * K + kg[i];
        gb[i] = Bw + (long)(bn * 128 + row[i]) * K + kg[i];
        soff[i] = (uint32_t)(row[i] * GKS + kg[i]) * 2;
    }

    const uint32_t as0 = cvta_s(As);
    const uint32_t bs0 = cvta_s(Bs);
    const int nsteps = K / 64;   // 12

#pragma unroll
    for (int st = 0; st < 2; st++) {
#pragma unroll
        for (int i = 0; i < 4; i++) {
            cp16(as0 + st * GST * 2 + soff[i], ga[i] + st * 64);
            cp16(bs0 + st * GST * 2 + soff[i], gb[i] + st * 64);
        }
        CP_COMMIT();
    }

    float acc[4][4][4];
#pragma unroll
    for (int mt = 0; mt < 4; mt++)
#pragma unroll
        for (int nt = 0; nt < 4; nt++)
#pragma unroll
            for (int r = 0; r < 4; r++) acc[mt][nt][r] = 0.f;

    int cur = 0;
    for (int kt = 0; kt < nsteps; kt++) {
        if (kt + 2 < nsteps) { CP_WAIT(1); } else { CP_WAIT(0); }
        __syncthreads();

        if (kt + 2 < nsteps) {
            int nst = cur + 2; if (nst >= 3) nst -= 3;
#pragma unroll
            for (int i = 0; i < 4; i++) {
                cp16(as0 + nst * GST * 2 + soff[i], ga[i] + (kt + 2) * 64);
                cp16(bs0 + nst * GST * 2 + soff[i], gb[i] + (kt + 2) * 64);
            }
            CP_COMMIT();
        }

        const uint32_t asb = as0 + (uint32_t)(cur * GST) * 2;
        const uint32_t bsb = bs0 + (uint32_t)(cur * GST) * 2;
#pragma unroll
        for (int kc = 0; kc < 4; kc++) {
            uint32_t af[4][4], bf[2][4];
#pragma unroll
            for (int mt = 0; mt < 4; mt++)
                ldsm4(af[mt], asb +
                    ((wm * 64 + mt * 16 + arow) * GKS + kc * 16 + acol) * 2);
#pragma unroll
            for (int p = 0; p < 2; p++)
                ldsm4(bf[p], bsb +
                    ((wn * 32 + p * 16 + brow) * GKS + kc * 16 + bcol) * 2);
#pragma unroll
            for (int mt = 0; mt < 4; mt++)
#pragma unroll
                for (int p = 0; p < 2; p++) {
                    mma_f16(acc[mt][2 * p],     af[mt], bf[p][0], bf[p][1]);
                    mma_f16(acc[mt][2 * p + 1], af[mt], bf[p][2], bf[p][3]);
                }
        }

        cur++; if (cur >= 3) cur = 0;
    }

    // ---------------- Fused bias + LayerNorm epilogue ----------------
    __syncthreads();                     // retire last ldsm before smem reuse
    float* redS = (float*)gsm;           // [2 wm][4 wn][16 rows]
    float* redV = redS + 128;

    const int sec = bn / 6;              // 0=q, 1=k, 2=v
    const int bi  = bn % 6;
    const int hh  = bi * 2 + (wn >> 1);  // head for this warp
    const int cih = (wn & 1) * 32;       // col-in-head base of this warp

    const float* gvec;
    const float* bvec;
    if (sec == 0) { gvec = z ? gqy : gqx; bvec = z ? bqy : bqx; }
    else          { gvec = z ? gky : gkx; bvec = z ? bky : bkx; }

    float2 bb[4], gg[4], bv[4];
#pragma unroll
    for (int nt = 0; nt < 4; nt++) {
        int nc = bn * 128 + wn * 32 + nt * 8 + 2 * tig;
        bb[nt] = *(const float2*)&bias[nc];
        if (sec < 2) {
            int c = cih + nt * 8 + 2 * tig;
            gg[nt] = *(const float2*)&gvec[c];
            bv[nt] = *(const float2*)&bvec[c];
        }
    }
    const float scl = (sec == 0) ? SCF : 1.0f;
    __half* dst = (sec == 0) ? Qh : (sec == 1) ? Kh : Vh;
    const int rbase = (wm * 4 + wn) * 16;

#pragma unroll
    for (int mt = 0; mt < 4; mt++) {
        float v0[8], v1[8];
#pragma unroll
        for (int nt = 0; nt < 4; nt++) {
            v0[nt * 2 + 0] = acc[mt][nt][0] + bb[nt].x;
            v0[nt * 2 + 1] = acc[mt][nt][1] + bb[nt].y;
            v1[nt * 2 + 0] = acc[mt][nt][2] + bb[nt].x;
            v1[nt * 2 + 1] = acc[mt][nt][3] + bb[nt].y;
        }

        int t0 = bm * 128 + wm * 64 + mt * 16 + gid;   // token (row)
        int b  = t0 >> 10, s = t0 & 1023;
        long o0 = (((long)(b * HEADS + hh)) * SFULL + z * SEQ + s) * HD + cih;
        long o1 = o0 + 8 * HD;                          // token t0+8, same chunk

        if (sec < 2) {
            // mean over 64 head cols (quad shuffle + warp-pair smem exchange)
            float s0 = 0.f, s1 = 0.f;
#pragma unroll
            for (int j = 0; j < 8; j++) { s0 += v0[j]; s1 += v1[j]; }
#pragma unroll
            for (int o = 1; o <= 2; o <<= 1) {
                s0 += __shfl_xor_sync(0xffffffffu, s0, o);
                s1 += __shfl_xor_sync(0xffffffffu, s1, o);
            }
            if (tig == 0) {
                redS[rbase + gid]     = s0;
                redS[rbase + gid + 8] = s1;
            }
            __syncthreads();
            int prb = (wm * 4 + (wn ^ 1)) * 16;
            float mu0 = (redS[rbase + gid]     + redS[prb + gid])     * (1.f / 64.f);
            float mu1 = (redS[rbase + gid + 8] + redS[prb + gid + 8]) * (1.f / 64.f);

            float q0 = 0.f, q1 = 0.f;
#pragma unroll
            for (int j = 0; j < 8; j++) {
                float d0 = v0[j] - mu0, d1 = v1[j] - mu1;
                q0 += d0 * d0; q1 += d1 * d1;
            }
#pragma unroll
            for (int o = 1; o <= 2; o <<= 1) {
                q0 += __shfl_xor_sync(0xffffffffu, q0, o);
                q1 += __shfl_xor_sync(0xffffffffu, q1, o);
            }
            if (tig == 0) {
                redV[rbase + gid]     = q0;
                redV[rbase + gid + 8] = q1;
            }
            __syncthreads();
            float var0 = (redV[rbase + gid]     + redV[prb + gid])     * (1.f / 64.f);
            float var1 = (redV[rbase + gid + 8] + redV[prb + gid + 8]) * (1.f / 64.f);
            float inv0 = rsqrtf(var0 + 1e-5f) * scl;
            float inv1 = rsqrtf(var1 + 1e-5f) * scl;

#pragma unroll
            for (int nt = 0; nt < 4; nt++) {
                int c = nt * 8 + 2 * tig;
                float a0 = (v0[nt*2+0] - mu0) * inv0 * gg[nt].x + bv[nt].x * scl;
                float a1 = (v0[nt*2+1] - mu0) * inv0 * gg[nt].y + bv[nt].y * scl;
                float c0 = (v1[nt*2+0] - mu1) * inv1 * gg[nt].x + bv[nt].x * scl;
                float c1 = (v1[nt*2+1] - mu1) * inv1 * gg[nt].y + bv[nt].y * scl;
                *(half2*)&dst[o0 + c] = __floats2half2_rn(a0, a1);
                *(half2*)&dst[o1 + c] = __floats2half2_rn(c0, c1);
            }
            __syncthreads();   // protect red arrays before next mt
        } else {
#pragma unroll
            for (int nt = 0; nt < 4; nt++) {
                int c = nt * 8 + 2 * tig;
                *(half2*)&dst[o0 + c] = __floats2half2_rn(v0[nt*2+0], v0[nt*2+1]);
                *(half2*)&dst[o1 + c] = __floats2half2_rn(v1[nt*2+0], v1[nt*2+1]);
            }
        }
    }
}

// ---------------------------------------------------------------------------
// Projection GEMM (unchanged from R16): BK=64, 3-stage ring, fp32 out.
// A rows addressed in 1024-row chunks (chunk stride a_bstride, half units).
// ---------------------------------------------------------------------------
__global__ void __launch_bounds__(256) gemm_proj(
        const __half* __restrict__ A0, const __half* __restrict__ A1,
        long a_bstride,
        const __half* __restrict__ B0, const __half* __restrict__ B1,
        const float* __restrict__ bias0, const float* __restrict__ bias1,
        float* __restrict__ C0, float* __restrict__ C1, int N, int K) {
    extern __shared__ __half gsm[];
    __half* As = gsm;
    __half* Bs = gsm + 3 * GST;

    const int z = blockIdx.z;
    const __half* A  = z ? A1 : A0;
    const __half* Bw = z ? B1 : B0;
    const float* bias = z ? bias1 : bias0;
    float* C = z ? C1 : C0;

    const int tid = threadIdx.x, lane = tid & 31, w = tid >> 5;
    const int gid = lane >> 2, tig = lane & 3;
    const int bm = blockIdx.y, bn = blockIdx.x;
    const int wm = w & 1, wn = w >> 1;

    const int arow = (lane & 7) + 8 * ((lane >> 3) & 1);
    const int acol = ((lane >> 4) & 1) * 8;
    const int brow = (lane & 7) + 8 * ((lane >> 4) & 1);
    const int bcol = ((lane >> 3) & 1) * 8;

    int row[4], kg[4];
    const __half* ga[4];
    const __half* gb[4];
    uint32_t soff[4];
#pragma unroll
    for (int i = 0; i < 4; i++) {
        int s = i * 256 + tid;
        row[i] = s >> 3;
        kg[i]  = (s & 7) * 8;
        int m = bm * 128 + row[i];
        ga[i] = A + ((long)(m >> 10)) * a_bstride + (long)(m & 1023) * K + kg[i];
        gb[i] = Bw + (long)(bn * 128 + row[i]) * K + kg[i];
        soff[i] = (uint32_t)(row[i] * GKS + kg[i]) * 2;
    }

    const uint32_t as0 = cvta_s(As);
    const uint32_t bs0 = cvta_s(Bs);
    const int nsteps = K / 64;

#pragma unroll
    for (int st = 0; st < 2; st++) {
#pragma unroll
        for (int i = 0; i < 4; i++) {
            cp16(as0 + st * GST * 2 + soff[i], ga[i] + st * 64);
            cp16(bs0 + st * GST * 2 + soff[i], gb[i] + st * 64);
        }
        CP_COMMIT();
    }

    float acc[4][4][4];
#pragma unroll
    for (int mt = 0; mt < 4; mt++)
#pragma unroll
        for (int nt = 0; nt < 4; nt++)
#pragma unroll
            for (int r = 0; r < 4; r++) acc[mt][nt][r] = 0.f;

    int cur = 0;
    for (int kt = 0; kt < nsteps; kt++) {
        if (kt + 2 < nsteps) { CP_WAIT(1); } else { CP_WAIT(0); }
        __syncthreads();

        if (kt + 2 < nsteps) {
            int nst = cur + 2; if (nst >= 3) nst -= 3;
#pragma unroll
            for (int i = 0; i < 4; i++) {
                cp16(as0 + nst * GST * 2 + soff[i], ga[i] + (kt + 2) * 64);
                cp16(bs0 + nst * GST * 2 + soff[i], gb[i] + (kt + 2) * 64);
            }
            CP_COMMIT();
        }

        const uint32_t asb = as0 + (uint32_t)(cur * GST) * 2;
        const uint32_t bsb = bs0 + (uint32_t)(cur * GST) * 2;
#pragma unroll
        for (int kc = 0; kc < 4; kc++) {
            uint32_t af[4][4], bf[2][4];
#pragma unroll
            for (int mt = 0; mt < 4; mt++)
                ldsm4(af[mt], asb +
                    ((wm * 64 + mt * 16 + arow) * GKS + kc * 16 + acol) * 2);
#pragma unroll
            for (int p = 0; p < 2; p++)
                ldsm4(bf[p], bsb +
                    ((wn * 32 + p * 16 + brow) * GKS + kc * 16 + bcol) * 2);
#pragma unroll
            for (int mt = 0; mt < 4; mt++)
#pragma unroll
                for (int p = 0; p < 2; p++) {
                    mma_f16(acc[mt][2 * p],     af[mt], bf[p][0], bf[p][1]);
                    mma_f16(acc[mt][2 * p + 1], af[mt], bf[p][2], bf[p][3]);
                }
        }

        cur++; if (cur >= 3) cur = 0;
    }

#pragma unroll
    for (int mt = 0; mt < 4; mt++) {
        int m0 = bm * 128 + wm * 64 + mt * 16 + gid;
#pragma unroll
        for (int nt = 0; nt < 4; nt++) {
            int n0 = bn * 128 + wn * 32 + nt * 8 + 2 * tig;
            float2 bbv = *(const float2*)&bias[n0];
            store2(C, (long)m0 * N + n0,
                   acc[mt][nt][0] + bbv.x, acc[mt][nt][1] + bbv.y);
            store2(C, (long)(m0 + 8) * N + n0,
                   acc[mt][nt][2] + bbv.x, acc[mt][nt][3] + bbv.y);
        }
    }
}

// ---------------------------------------------------------------------------
// fp16 flash attention (unchanged from R14): 4 warps x 32 q, K-tiles of 64,
// 3-stage cp.async ring, K frags shared across q row-tiles, fixed softmax,
// l via ones-MMA. Output [b, s, h, d] half.
// ---------------------------------------------------------------------------
#define AS 72
#define STG_H (64 * AS)
#define ATTN_SMEM (3 * 2 * STG_H * 2)

__global__ void __launch_bounds__(128, 3) attn_h(
        const __half* __restrict__ Q, const __half* __restrict__ K,
        const __half* __restrict__ V, __half* __restrict__ O) {
    extern __shared__ __half smh[];
    __half* KsS = smh;
    __half* VsS = smh + 3 * STG_H;

    const int tid = threadIdx.x, lane = tid & 31, w = tid >> 5;
    const int gid = lane >> 2, tig = lane & 3;
    const int h = blockIdx.y, b = blockIdx.z;
    const long bh = ((long)(b * HEADS + h)) * (SFULL * HD);
    const int q0 = blockIdx.x * 128;

    const int arow = (lane & 7) + 8 * ((lane >> 3) & 1);
    const int acol = ((lane >> 4) & 1) * 8;
    const int brow = (lane & 7) + 8 * ((lane >> 4) & 1);
    const int bcol = ((lane >> 3) & 1) * 8;

    const uint32_t ks0 = cvta_s(KsS);
    const uint32_t vs0 = cvta_s(VsS);

#pragma unroll
    for (int i = 0; i < 8; i++) {
        int s = i * 128 + tid;
        int r = s >> 3, c = (s & 7) * 8;
        uint4 v = *(const uint4*)(Q + bh + (long)(q0 + r) * HD + c);
        if (r < 64) *(uint4*)&KsS[r * AS + c] = v;
        else        *(uint4*)&VsS[(r - 64) * AS + c] = v;
    }
    __syncthreads();
    uint32_t qa[2][4][4];
#pragma unroll
    for (int rt = 0; rt < 2; rt++) {
        int qrow = w * 32 + rt * 16;
        uint32_t basea = (qrow < 64)
            ? ks0 + (uint32_t)((qrow + arow) * AS) * 2
            : vs0 + (uint32_t)((qrow - 64 + arow) * AS) * 2;
#pragma unroll
        for (int kc = 0; kc < 4; kc++)
            ldsm4(qa[rt][kc], basea + (kc * 16 + acol) * 2);
    }
    __syncthreads();

    float acc[2][8][4];
    float accl[2][4];
#pragma unroll
    for (int rt = 0; rt < 2; rt++) {
#pragma unroll
        for (int r = 0; r < 4; r++) accl[rt][r] = 0.f;
#pragma unroll
        for (int nt = 0; nt < 8; nt++)
#pragma unroll
            for (int r = 0; r < 4; r++) acc[rt][nt][r] = 0.f;
    }
    const uint32_t ONE2 = 0x3C003C00u;

    int srow[4], scol[4];
#pragma unroll
    for (int i = 0; i < 4; i++) {
        int s = i * 128 + tid;
        srow[i] = s >> 3;
        scol[i] = (s & 7) * 8;
    }

#pragma unroll
    for (int st = 0; st < 2; st++) {
#pragma unroll
        for (int i = 0; i < 4; i++) {
            uint32_t so = (uint32_t)(st * STG_H + srow[i] * AS + scol[i]) * 2;
            long go = (long)(st * 64 + srow[i]) * HD + scol[i];
            cp16(ks0 + so, K + bh + go);
            cp16(vs0 + so, V + bh + go);
        }
        CP_COMMIT();
    }

    const int NT = SFULL / 64;
    int cur = 0;
    for (int t = 0; t < NT; t++) {
        if (t + 2 < NT) { CP_WAIT(1); } else { CP_WAIT(0); }
        __syncthreads();

        if (t + 2 < NT) {
            int nst = cur + 2; if (nst >= 3) nst -= 3;
#pragma unroll
            for (int i = 0; i < 4; i++) {
                uint32_t so = (uint32_t)(nst * STG_H + srow[i] * AS + scol[i]) * 2;
                long go = (long)((t + 2) * 64 + srow[i]) * HD + scol[i];
                cp16(ks0 + so, K + bh + go);
                cp16(vs0 + so, V + bh + go);
            }
            CP_COMMIT();
        }

        const uint32_t kc_base = ks0 + (uint32_t)(cur * STG_H) * 2;
        const uint32_t vc_base = vs0 + (uint32_t)(cur * STG_H) * 2;

        uint32_t pf[2][4][4];
#pragma unroll
        for (int p = 0; p < 4; p++) {
            float s0[2][4] = {{0.f, 0.f, 0.f, 0.f}, {0.f, 0.f, 0.f, 0.f}};
            float s1[2][4] = {{0.f, 0.f, 0.f, 0.f}, {0.f, 0.f, 0.f, 0.f}};
#pragma unroll
            for (int kc = 0; kc < 4; kc++) {
                uint32_t kb[4];
                ldsm4(kb, kc_base +
                    ((p * 16 + brow) * AS + kc * 16 + bcol) * 2);
#pragma unroll
                for (int rt = 0; rt < 2; rt++) {
                    mma_f16(s0[rt], qa[rt][kc], kb[0], kb[1]);
                    mma_f16(s1[rt], qa[rt][kc], kb[2], kb[3]);
                }
            }
#pragma unroll
            for (int rt = 0; rt < 2; rt++) {
                pf[rt][p][0] = h2exp2(packh2(s0[rt][0], s0[rt][1]));
                pf[rt][p][1] = h2exp2(packh2(s0[rt][2], s0[rt][3]));
                pf[rt][p][2] = h2exp2(packh2(s1[rt][0], s1[rt][1]));
                pf[rt][p][3] = h2exp2(packh2(s1[rt][2], s1[rt][3]));
                mma_f16(accl[rt], pf[rt][p], ONE2, ONE2);
            }
        }

#pragma unroll
        for (int kc = 0; kc < 4; kc++) {
#pragma unroll
            for (int p = 0; p < 4; p++) {
                uint32_t vb[4];
                ldsm4t(vb, vc_base +
                    ((kc * 16 + arow) * AS + p * 16 + acol) * 2);
#pragma unroll
                for (int rt = 0; rt < 2; rt++) {
                    mma_f16(acc[rt][2 * p],     pf[rt][kc], vb[0], vb[1]);
                    mma_f16(acc[rt][2 * p + 1], pf[rt][kc], vb[2], vb[3]);
                }
            }
        }

        cur++; if (cur >= 3) cur = 0;
    }

#pragma unroll
    for (int rt = 0; rt < 2; rt++) {
        float inv0 = 1.0f / accl[rt][0];
        float inv1 = 1.0f / accl[rt][2];
        int sg = q0 + w * 32 + rt * 16 + gid;
        long ob0 = (((long)(b * SFULL + sg))     * HEADS + h) * HD;
        long ob1 = (((long)(b * SFULL + sg + 8)) * HEADS + h) * HD;
#pragma unroll
        for (int nt = 0; nt < 8; nt++) {
            int c = nt * 8 + 2 * tig;
            *(half2*)&O[ob0 + c] = __floats2half2_rn(acc[rt][nt][0] * inv0,
                                                     acc[rt][nt][1] * inv0);
            *(half2*)&O[ob1 + c] = __floats2half2_rn(acc[rt][nt][2] * inv1,
                                                     acc[rt][nt][3] * inv1);
        }
    }
}

// ---------------------------------------------------------------------------
// Launch
// ---------------------------------------------------------------------------
extern "C" void kernel_launch(void* const* d_in, const int* in_sizes, int n_in,
                              void* d_out, int out_size) {
    const float* x       = (const float*)d_in[0];
    const float* y       = (const float*)d_in[1];
    const float* Wqkv_x  = (const float*)d_in[2];
    const float* bqkv_x  = (const float*)d_in[3];
    const float* Wqkv_y  = (const float*)d_in[4];
    const float* bqkv_y  = (const float*)d_in[5];
    const float* Wproj_x = (const float*)d_in[6];
    const float* bproj_x = (const float*)d_in[7];
    const float* Wproj_y = (const float*)d_in[8];
    const float* bproj_y = (const float*)d_in[9];
    const float* gq_x    = (const float*)d_in[10];
    const float* bq_x    = (const float*)d_in[11];
    const float* gk_x    = (const float*)d_in[12];
    const float* bk_x    = (const float*)d_in[13];
    const float* gq_y    = (const float*)d_in[14];
    const float* bq_y    = (const float*)d_in[15];
    const float* gk_y    = (const float*)d_in[16];
    const float* bk_y    = (const float*)d_in[17];
    float* out = (float*)d_out;

    __half *xh, *yh, *wqx, *wqy, *wpx, *wpy, *Qh, *Kh, *Vh, *Oh;
    cudaGetSymbolAddress((void**)&xh,  g_xh);
    cudaGetSymbolAddress((void**)&yh,  g_yh);
    cudaGetSymbolAddress((void**)&wqx, g_wqx);
    cudaGetSymbolAddress((void**)&wqy, g_wqy);
    cudaGetSymbolAddress((void**)&wpx, g_wpx);
    cudaGetSymbolAddress((void**)&wpy, g_wpy);
    cudaGetSymbolAddress((void**)&Qh,  g_Qh);
    cudaGetSymbolAddress((void**)&Kh,  g_Kh);
    cudaGetSymbolAddress((void**)&Vh,  g_Vh);
    cudaGetSymbolAddress((void**)&Oh,  g_Oh);

    cudaFuncSetAttribute(attn_h,
                         cudaFuncAttributeMaxDynamicSharedMemorySize,
                         ATTN_SMEM);
    cudaFuncSetAttribute(gemm_qkv_ln,
                         cudaFuncAttributeMaxDynamicSharedMemorySize,
                         GEMM_SMEM);
    cudaFuncSetAttribute(gemm_proj,
                         cudaFuncAttributeMaxDynamicSharedMemorySize,
                         GEMM_SMEM);

    // Prep: convert all inputs/weights to fp16 in one launch
    cvt_all<<<NCVT / 256, 256>>>(x, y, Wqkv_x, Wqkv_y, Wproj_x, Wproj_y,
                                 xh, yh, wqx, wqy, wpx, wpy);

    // QKV projections + fused bias/LayerNorm epilogue for both streams:
    // writes Qh (pre-scaled), Kh, Vh directly.
    gemm_qkv_ln<<<dim3(QKVN / 128, MTOK / 128, 2), 256, GEMM_SMEM>>>(
        xh, yh, wqx, wqy, bqkv_x, bqkv_y, Qh, Kh, Vh,
        gq_x, bq_x, gk_x, bk_x, gq_y, bq_y, gk_y, bk_y);

    // Attention: 128 q per block, 3-stage cp.async ring
    attn_h<<<dim3(SFULL / 128, HEADS, BATCH), 128, ATTN_SMEM>>>(
        Qh, Kh, Vh, Oh);

    // Output projections for both streams (float output)
    gemm_proj<<<dim3(DIM / 128, MTOK / 128, 2), 256, GEMM_SMEM>>>(
        Oh, Oh + (long)SEQ * DIM, (long)SFULL * DIM, wpx, wpy,
        bproj_x, bproj_y, out, out + (long)MTOK * DIM, DIM, DIM);
}